// round 14
// baseline (speedup 1.0000x reference)
#include <cuda_runtime.h>
#include <cuda_bf16.h>
#include <cuda_fp16.h>
#include <cstdint>
#include <math.h>

#define Bn 32
#define Dn 512
#define Tn 32
#define Nn 64
#define Hn 8
#define DKn 64
#define FFn 2048
#define MTOT (Bn * Nn * Tn)
#define SCALE_F 0.022097086912079608f
#define LN_EPS 1e-5f

// ------------------------------------------------------------------
// Scratch. bf16-typed half buffers hold FP16 bits.
// ------------------------------------------------------------------
__device__ float g_XR[(size_t)MTOT * Dn];
__device__ float g_Y1[(size_t)MTOT * Dn];
__device__ float g_X1[(size_t)MTOT * Dn];
__device__ float g_FF[(size_t)MTOT * Dn];
__device__ __nv_bfloat16 g_QKh[(size_t)MTOT * 1024];    // fp16
__device__ __nv_bfloat16 g_Vmh[(size_t)MTOT * Dn];      // fp16
__device__ __nv_bfloat16 g_XRh[(size_t)MTOT * Dn];      // fp16
__device__ __nv_bfloat16 g_XPEh[(size_t)MTOT * Dn];     // fp16
__device__ __nv_bfloat16 g_ATTh[(size_t)MTOT * Dn];     // fp16
__device__ __nv_bfloat16 g_X1h[(size_t)MTOT * Dn];      // fp16
__device__ __nv_bfloat16 g_Hh[(size_t)MTOT * FFn];      // fp16
__device__ __nv_bfloat16 g_Wqkh[1024 * Dn];             // fp16
__device__ __nv_bfloat16 g_Wvh[Dn * Dn];                // fp16
__device__ __nv_bfloat16 g_Woh[Dn * Dn];                // fp16
__device__ __nv_bfloat16 g_W1h[FFn * Dn];               // fp16
__device__ __nv_bfloat16 g_W2h[Dn * FFn];               // fp16
__device__ float g_bqk[1024];
__device__ float2 g_part[Bn * 32];
__device__ float2 g_stats[Bn];

// ------------------------------------------------------------------
__device__ __forceinline__ uint32_t smem_u32(const void* p) {
    uint32_t a;
    asm("{ .reg .u64 t; cvta.to.shared.u64 t, %1; cvt.u32.u64 %0, t; }" : "=r"(a) : "l"(p));
    return a;
}
__device__ __forceinline__ void cpasync16(uint32_t dst, const void* src) {
    asm volatile("cp.async.cg.shared.global [%0], [%1], 16;" :: "r"(dst), "l"(src));
}
#define CP_COMMIT() asm volatile("cp.async.commit_group;" ::: "memory")
#define CP_WAIT0() asm volatile("cp.async.wait_group 0;" ::: "memory")

#define LDSM4(r0, r1, r2, r3, addr) \
    asm volatile("ldmatrix.sync.aligned.m8n8.x4.shared.b16 {%0,%1,%2,%3}, [%4];" \
                 : "=r"(r0), "=r"(r1), "=r"(r2), "=r"(r3) : "r"(addr))

#define LDSM4T(r0, r1, r2, r3, addr) \
    asm volatile("ldmatrix.sync.aligned.m8n8.x4.trans.shared.b16 {%0,%1,%2,%3}, [%4];" \
                 : "=r"(r0), "=r"(r1), "=r"(r2), "=r"(r3) : "r"(addr))

#define MMA_F16(d, a, b) \
    asm volatile("mma.sync.aligned.m16n8k16.row.col.f32.f16.f16.f32 " \
                 "{%0,%1,%2,%3}, {%4,%5,%6,%7}, {%8,%9}, {%0,%1,%2,%3};" \
                 : "+f"((d)[0]), "+f"((d)[1]), "+f"((d)[2]), "+f"((d)[3]) \
                 : "r"((a)[0]), "r"((a)[1]), "r"((a)[2]), "r"((a)[3]), \
                   "r"((b)[0]), "r"((b)[1]))

__device__ __forceinline__ uint32_t h2bits(float a, float b) {
    __half2 h = __floats2half2_rn(a, b);
    return *(uint32_t*)&h;
}

// ------------------------------------------------------------------
// weight conversion -> fp16; bias concat
// ------------------------------------------------------------------
__global__ void conv_all(const float* __restrict__ Wq, const float* __restrict__ Wk,
                         const float* __restrict__ Wv, const float* __restrict__ Wo,
                         const float* __restrict__ W1, const float* __restrict__ W2,
                         const float* __restrict__ bq, const float* __restrict__ bk) {
    long i4 = (long)blockIdx.x * 256 + threadIdx.x;
    if (i4 >= 786432) {
        int t = threadIdx.x;
        if (blockIdx.x == 3072) {
            g_bqk[t] = bq[t];
            g_bqk[t + 256] = bq[t + 256];
            g_bqk[t + 512] = bk[t];
            g_bqk[t + 768] = bk[t + 256];
        }
        return;
    }
    const float* src;
    __nv_bfloat16* dh;
    long o;
    if (i4 < 65536)       { src = Wq; dh = g_Wqkh;          o = i4; }
    else if (i4 < 131072) { src = Wk; dh = g_Wqkh + 262144; o = i4 - 65536; }
    else if (i4 < 196608) { src = Wv; dh = g_Wvh;           o = i4 - 131072; }
    else if (i4 < 262144) { src = Wo; dh = g_Woh;           o = i4 - 196608; }
    else if (i4 < 524288) { src = W1; dh = g_W1h;           o = i4 - 262144; }
    else                  { src = W2; dh = g_W2h;           o = i4 - 524288; }
    long e = o * 4;
    float4 v = *(const float4*)&src[e];
    *(uint2*)&dh[e] = make_uint2(h2bits(v.x, v.y), h2bits(v.z, v.w));
}

// ------------------------------------------------------------------
__global__ void prep_xr(const float* __restrict__ x, const float* __restrict__ pe,
                        float* __restrict__ XR,
                        __nv_bfloat16* __restrict__ XRh, __nv_bfloat16* __restrict__ XPEh) {
    __shared__ float tile[32][33];
    int bt = blockIdx.z;
    int b = bt >> 5, t = bt & 31;
    int d0 = blockIdx.x * 32, n0 = blockIdx.y * 32;
    size_t bbase = (size_t)b * (Dn * Tn * Nn);
#pragma unroll
    for (int i = 0; i < 4; i++) {
        int d = d0 + threadIdx.y + i * 8;
        tile[threadIdx.y + i * 8][threadIdx.x] =
            x[bbase + (size_t)d * (Tn * Nn) + t * Nn + n0 + threadIdx.x];
    }
    __syncthreads();
    int d = d0 + threadIdx.x;
#pragma unroll
    for (int i = 0; i < 4; i++) {
        int n = n0 + threadIdx.y + i * 8;
        float v = tile[threadIdx.x][threadIdx.y + i * 8];
        size_t idx = bbase + (size_t)n * (Tn * Dn) + t * Dn + d;
        XR[idx] = v;
        __half hv = __float2half_rn(v);
        *(uint16_t*)&XRh[idx] = *(uint16_t*)&hv;
        __half hp = __float2half_rn(v + pe[n * Dn + d]);
        *(uint16_t*)&XPEh[idx] = *(uint16_t*)&hp;
    }
}

__global__ void out_tr(const float* __restrict__ FF, float* __restrict__ out) {
    __shared__ float tile[32][33];
    int bt = blockIdx.z;
    int b = bt >> 5, t = bt & 31;
    int d0 = blockIdx.x * 32, n0 = blockIdx.y * 32;
    size_t bbase = (size_t)b * (Dn * Tn * Nn);
#pragma unroll
    for (int i = 0; i < 4; i++) {
        int n = n0 + threadIdx.y + i * 8;
        tile[threadIdx.y + i * 8][threadIdx.x] =
            FF[bbase + (size_t)n * (Tn * Dn) + t * Dn + d0 + threadIdx.x];
    }
    __syncthreads();
#pragma unroll
    for (int i = 0; i < 4; i++) {
        int d = d0 + threadIdx.y + i * 8;
        out[bbase + (size_t)d * (Tn * Nn) + t * Nn + n0 + threadIdx.x] =
            tile[threadIdx.x][threadIdx.y + i * 8];
    }
}

// ------------------------------------------------------------------
// fp16 GEMM: 256x128 CTA tile, 512 threads (16 warps, 8x2),
// warp tile 32x64, BK=128, 2-stage, 1 barrier/iter, pitch-272 smem,
// prefetch spread over 6 kc.  OUTM_: 0=float, 2=fp16
// ------------------------------------------------------------------
#define PITCHB 272
#define STG_B (384 * PITCHB)            // 104448
#define GEMM_DSMEM (2 * STG_B)          // 208896

template <bool BIAS_, bool RELU_, bool RESID_, int OUTM_>
__global__ void __launch_bounds__(512, 1)
gemm_mma(const __nv_bfloat16* __restrict__ Ah, const __nv_bfloat16* __restrict__ Wh,
         const float* __restrict__ bias, const float* __restrict__ Rsd,
         float* __restrict__ Cf, __nv_bfloat16* __restrict__ Ch,
         int Ncols, int K) {
    constexpr uint32_t oAH = 0;
    constexpr uint32_t oBH = 256 * PITCHB;

    extern __shared__ char smraw[];
    const uint32_t sb = smem_u32(smraw);
    const int tid = threadIdx.x;
    const int wid = tid >> 5;
    const int lane = tid & 31;
    const size_t rowBase = (size_t)blockIdx.y * 256;
    const int colBase = blockIdx.x * 128;
    const int wm = (wid >> 1) * 32;   // 0..224
    const int wn = (wid & 1) * 64;    // 0,64

    float acc[2][8][4];
#pragma unroll
    for (int mt = 0; mt < 2; mt++)
#pragma unroll
        for (int nt = 0; nt < 8; nt++)
#pragma unroll
            for (int q = 0; q < 4; q++) acc[mt][nt][q] = 0.f;

    const int KIT = K >> 7;

    // load 64 rows (16 chunks of 16B per row) with 512 threads: 2 chunks/thread
    auto load64 = [&](uint32_t sdst, const __nv_bfloat16* g, size_t row0, int k0, int r0) {
        const char* gbase = (const char*)(g + (row0 + r0) * (size_t)K + k0);
        size_t rs = (size_t)K * 2;
#pragma unroll
        for (int q = 0; q < 2; q++) {
            int ch = tid + q * 512;
            int r = ch >> 4, c = ch & 15;
            cpasync16(sdst + (r0 + r) * PITCHB + c * 16, gbase + (size_t)r * rs + c * 16);
        }
    };

#pragma unroll
    for (int r0 = 0; r0 < 256; r0 += 64) load64(sb + oAH, Ah, rowBase, 0, r0);
    load64(sb + oBH, Wh, (size_t)colBase, 0, 0);
    load64(sb + oBH, Wh, (size_t)colBase, 0, 64);
    CP_COMMIT();

    const int arow = lane & 15;
    const int ainc = lane >> 4;
    const int brow = (lane & 7) + ((lane >> 4) << 3);
    const int binc = (lane >> 3) & 1;

    for (int it = 0; it < KIT; ++it) {
        CP_WAIT0();
        __syncthreads();
        const bool pf = (it + 1 < KIT);
        const uint32_t stn = sb + ((it + 1) & 1) * STG_B;
        const int k0n = (it + 1) * 128;
        const uint32_t stb = sb + (it & 1) * STG_B;
#pragma unroll
        for (int kc = 0; kc < 8; kc++) {
            uint32_t ah[2][4], bh[8][2];
#pragma unroll
            for (int mt = 0; mt < 2; mt++) {
                uint32_t ad = stb + oAH + (wm + mt * 16 + arow) * PITCHB + kc * 32 + ainc * 16;
                LDSM4(ah[mt][0], ah[mt][1], ah[mt][2], ah[mt][3], ad);
            }
#pragma unroll
            for (int bt = 0; bt < 4; bt++) {
                uint32_t bd = stb + oBH + (wn + bt * 16 + brow) * PITCHB + kc * 32 + binc * 16;
                uint32_t r0, r1, r2, r3;
                LDSM4(r0, r1, r2, r3, bd);
                bh[2 * bt][0] = r0; bh[2 * bt][1] = r1;
                bh[2 * bt + 1][0] = r2; bh[2 * bt + 1][1] = r3;
            }
            if (pf) {
                if (kc < 4)       load64(stn + oAH, Ah, rowBase, k0n, kc * 64);
                else if (kc == 4) load64(stn + oBH, Wh, (size_t)colBase, k0n, 0);
                else if (kc == 5) load64(stn + oBH, Wh, (size_t)colBase, k0n, 64);
            }
#pragma unroll
            for (int mt = 0; mt < 2; mt++) {
#pragma unroll
                for (int nt = 0; nt < 8; nt++) {
                    MMA_F16(acc[mt][nt], ah[mt], bh[nt]);
                }
            }
        }
        CP_COMMIT();
    }

    // epilogue
#pragma unroll
    for (int mt = 0; mt < 2; mt++) {
#pragma unroll
        for (int nt = 0; nt < 8; nt++) {
            const int col = colBase + wn + nt * 8 + (lane & 3) * 2;
#pragma unroll
            for (int half = 0; half < 2; half++) {
                const size_t row = rowBase + wm + mt * 16 + (lane >> 2) + half * 8;
                float vx = acc[mt][nt][half * 2 + 0];
                float vy = acc[mt][nt][half * 2 + 1];
                if (BIAS_) {
                    float2 bv = *(const float2*)&bias[col];
                    vx += bv.x; vy += bv.y;
                }
                if (RELU_) { vx = fmaxf(vx, 0.f); vy = fmaxf(vy, 0.f); }
                if (RESID_) {
                    float2 rv = *(const float2*)&Rsd[row * Ncols + col];
                    vx += rv.x; vy += rv.y;
                }
                if (OUTM_ == 0) {
                    *(float2*)&Cf[row * Ncols + col] = make_float2(vx, vy);
                } else {
                    *(uint32_t*)&Ch[row * Ncols + col] = h2bits(vx, vy);
                }
            }
        }
    }
}

// ------------------------------------------------------------------
// Tensor-core attention (unchanged from R13)
// ------------------------------------------------------------------
#define AP 144
__global__ void __launch_bounds__(256)
attn_tc(const __nv_bfloat16* __restrict__ QKh, const __nv_bfloat16* __restrict__ Vmh,
        const float* __restrict__ adj, const float* __restrict__ hw,
        __nv_bfloat16* __restrict__ ATTh) {
    __shared__ __align__(16) char sQ[64 * AP];
    __shared__ __align__(16) char sK[64 * AP];
    __shared__ __align__(16) char sA[64 * AP];
    __shared__ float sS[64][68];

    const int b = blockIdx.x >> 3;
    const int h = blockIdx.x & 7;
    const int tid = threadIdx.x;
    const int wid = tid >> 5;
    const int lane = tid & 31;
    const int wm = (wid >> 1) * 16;
    const int wn = (wid & 1) * 32;
    const uint32_t uQ = smem_u32(sQ);
    const uint32_t uK = smem_u32(sK);
    const uint32_t uA = smem_u32(sA);

    const int arow = lane & 15;
    const int ainc = lane >> 4;
    const int brow = (lane & 7) + ((lane >> 4) << 3);
    const int binc = (lane >> 3) & 1;
    const int tkrow = (lane & 7) + (((lane >> 3) & 1) << 3);
    const int tncol = (lane >> 4) * 8;

    const size_t tokBase = (size_t)b * 2048;
    const int lr = tid >> 3;
    const int lc = tid & 7;

    float acc[4][4];
#pragma unroll
    for (int nt = 0; nt < 4; nt++)
#pragma unroll
        for (int q = 0; q < 4; q++) acc[nt][q] = 0.f;

    for (int t0 = 0; t0 < 32; t0++) {
        __syncthreads();
#pragma unroll
        for (int j = 0; j < 2; j++) {
            int r = lr + j * 32;
            const __nv_bfloat16* qsrc = QKh + (tokBase + r * 32 + t0) * 1024 + h * DKn;
            cpasync16(uQ + r * AP + lc * 16, (const char*)qsrc + lc * 16);
            cpasync16(uK + r * AP + lc * 16, (const char*)(qsrc + 512) + lc * 16);
        }
        CP_COMMIT();
        CP_WAIT0();
        __syncthreads();
#pragma unroll
        for (int kc = 0; kc < 4; kc++) {
            uint32_t a[4], bf[4][2];
            LDSM4(a[0], a[1], a[2], a[3], uQ + (wm + arow) * AP + kc * 32 + ainc * 16);
#pragma unroll
            for (int bt = 0; bt < 2; bt++) {
                uint32_t r0, r1, r2, r3;
                LDSM4(r0, r1, r2, r3, uK + (wn + bt * 16 + brow) * AP + kc * 32 + binc * 16);
                bf[2 * bt][0] = r0; bf[2 * bt][1] = r1;
                bf[2 * bt + 1][0] = r2; bf[2 * bt + 1][1] = r3;
            }
#pragma unroll
            for (int nt = 0; nt < 4; nt++) MMA_F16(acc[nt], a, bf[nt]);
        }
    }

    __syncthreads();
#pragma unroll
    for (int nt = 0; nt < 4; nt++) {
        int col = wn + nt * 8 + (lane & 3) * 2;
#pragma unroll
        for (int half = 0; half < 2; half++) {
            int row = wm + (lane >> 2) + half * 8;
            sS[row][col] = acc[nt][half * 2] * SCALE_F;
            sS[row][col + 1] = acc[nt][half * 2 + 1] * SCALE_F;
        }
    }
    __syncthreads();

    {
        const int w = wid, ln2 = lane;
        const float hwv = hw[h];
        for (int rr = 0; rr < 8; rr++) {
            int row = w * 8 + rr;
            float v0 = sS[row][ln2];
            float v1 = sS[row][ln2 + 32];
            float mx = fmaxf(v0, v1);
#pragma unroll
            for (int o = 16; o; o >>= 1) mx = fmaxf(mx, __shfl_xor_sync(0xffffffffu, mx, o));
            float e0 = __expf(v0 - mx), e1 = __expf(v1 - mx);
            float s = e0 + e1;
#pragma unroll
            for (int o = 16; o; o >>= 1) s += __shfl_xor_sync(0xffffffffu, s, o);
            float inv = 1.f / s;
            size_t ab = (size_t)h * 4096 + row * 64;
            sS[row][ln2]      = e0 * inv * hwv + adj[ab + ln2];
            sS[row][ln2 + 32] = e1 * inv * hwv + adj[ab + 32 + ln2];
        }
    }
    __syncthreads();

    {
        int q = tid >> 2, mb = (tid & 3) * 16;
#pragma unroll
        for (int m = 0; m < 16; m += 2) {
            *(uint32_t*)(sA + q * AP + (mb + m) * 2) = h2bits(sS[q][mb + m], sS[q][mb + m + 1]);
        }
    }

    for (int t0 = 0; t0 < 32; t0++) {
        __syncthreads();
#pragma unroll
        for (int j = 0; j < 2; j++) {
            int r = lr + j * 32;
            const __nv_bfloat16* vsrc = Vmh + (tokBase + r * 32 + t0) * 512 + h * DKn;
            cpasync16(uK + r * AP + lc * 16, (const char*)vsrc + lc * 16);
        }
        CP_COMMIT();
        CP_WAIT0();
        __syncthreads();
        float o2[4][4];
#pragma unroll
        for (int nt = 0; nt < 4; nt++)
#pragma unroll
            for (int q = 0; q < 4; q++) o2[nt][q] = 0.f;
#pragma unroll
        for (int kc = 0; kc < 4; kc++) {
            uint32_t a[4], bf[4][2];
            LDSM4(a[0], a[1], a[2], a[3], uA + (wm + arow) * AP + kc * 32 + ainc * 16);
#pragma unroll
            for (int bt = 0; bt < 2; bt++) {
                uint32_t r0, r1, r2, r3;
                LDSM4T(r0, r1, r2, r3,
                       uK + (kc * 16 + tkrow) * AP + (wn + bt * 16 + tncol) * 2);
                bf[2 * bt][0] = r0; bf[2 * bt][1] = r1;
                bf[2 * bt + 1][0] = r2; bf[2 * bt + 1][1] = r3;
            }
#pragma unroll
            for (int nt = 0; nt < 4; nt++) MMA_F16(o2[nt], a, bf[nt]);
        }
#pragma unroll
        for (int nt = 0; nt < 4; nt++) {
            int dk = wn + nt * 8 + (lane & 3) * 2;
#pragma unroll
            for (int half = 0; half < 2; half++) {
                int qrow = wm + (lane >> 2) + half * 8;
                size_t off = (tokBase + qrow * 32 + t0) * 512 + h * DKn + dk;
                *(uint32_t*)&ATTh[off] = h2bits(o2[nt][half * 2], o2[nt][half * 2 + 1]);
            }
        }
    }
}

// ------------------------------------------------------------------
// LayerNorm
// ------------------------------------------------------------------
__global__ void ln_partial(const float* __restrict__ Y1, float2* __restrict__ part) {
    const int c = blockIdx.x, b = blockIdx.y;
    const float* p = Y1 + (size_t)b * 1048576 + (size_t)c * 32768;
    float s = 0.f, s2 = 0.f;
    for (int i = threadIdx.x; i < 32768; i += 256) {
        float v = p[i];
        s += v; s2 += v * v;
    }
    __shared__ float rs[256], rs2[256];
    rs[threadIdx.x] = s; rs2[threadIdx.x] = s2;
    __syncthreads();
    for (int o = 128; o; o >>= 1) {
        if (threadIdx.x < o) {
            rs[threadIdx.x] += rs[threadIdx.x + o];
            rs2[threadIdx.x] += rs2[threadIdx.x + o];
        }
        __syncthreads();
    }
    if (threadIdx.x == 0) part[b * 32 + c] = make_float2(rs[0], rs2[0]);
}

__global__ void ln_final(const float2* __restrict__ part, float2* __restrict__ stats) {
    int b = threadIdx.x;
    if (b < Bn) {
        float s = 0.f, s2 = 0.f;
        for (int c = 0; c < 32; c++) {
            float2 p = part[b * 32 + c];
            s += p.x; s2 += p.y;
        }
        const float invN = 1.0f / 1048576.0f;
        float mean = s * invN;
        float var = s2 * invN - mean * mean;
        stats[b] = make_float2(mean, rsqrtf(var + LN_EPS));
    }
}

__global__ void ln_apply(const float* __restrict__ Y1, const float2* __restrict__ stats,
                         const float* __restrict__ g1, const float* __restrict__ be1,
                         float* __restrict__ X1, __nv_bfloat16* __restrict__ X1h) {
    size_t e = ((size_t)blockIdx.x * blockDim.x + threadIdx.x) * 4;
    float2 st = stats[e >> 20];
    size_t gi = e & 1048575;
    float4 y = *(const float4*)&Y1[e];
    float4 g = *(const float4*)&g1[gi];
    float4 be = *(const float4*)&be1[gi];
    float4 o;
    o.x = (y.x - st.x) * st.y * g.x + be.x;
    o.y = (y.y - st.x) * st.y * g.y + be.y;
    o.z = (y.z - st.x) * st.y * g.z + be.z;
    o.w = (y.w - st.x) * st.y * g.w + be.w;
    *(float4*)&X1[e] = o;
    *(uint2*)&X1h[e] = make_uint2(h2bits(o.x, o.y), h2bits(o.z, o.w));
}

// ------------------------------------------------------------------
extern "C" void kernel_launch(void* const* d_in, const int* in_sizes, int n_in,
                              void* d_out, int out_size) {
    const float* x   = (const float*)d_in[0];
    const float* Wq  = (const float*)d_in[1];
    const float* bq  = (const float*)d_in[2];
    const float* Wk  = (const float*)d_in[3];
    const float* bk  = (const float*)d_in[4];
    const float* Wv  = (const float*)d_in[5];
    const float* bv  = (const float*)d_in[6];
    const float* Wo  = (const float*)d_in[7];
    const float* bo  = (const float*)d_in[8];
    const float* W1  = (const float*)d_in[9];
    const float* b1  = (const float*)d_in[10];
    const float* W2  = (const float*)d_in[11];
    const float* b2  = (const float*)d_in[12];
    const float* g1  = (const float*)d_in[13];
    const float* be1 = (const float*)d_in[14];
    const float* adj = (const float*)d_in[15];
    const float* hw  = (const float*)d_in[16];
    const float* pe  = (const float*)d_in[17];
    float* out = (float*)d_out;

#define GETP(sym, ty, name) ty* name; { void* _p; cudaGetSymbolAddress(&_p, sym); name = (ty*)_p; }
    GETP(g_XR, float, XR) GETP(g_Y1, float, Y1) GETP(g_X1, float, X1) GETP(g_FF, float, FFo)
    GETP(g_QKh, __nv_bfloat16, QKh)
    GETP(g_Vmh, __nv_bfloat16, Vmh)
    GETP(g_XRh, __nv_bfloat16, XRh)
    GETP(g_XPEh, __nv_bfloat16, XPEh)
    GETP(g_ATTh, __nv_bfloat16, ATTh)
    GETP(g_X1h, __nv_bfloat16, X1h)
    GETP(g_Hh, __nv_bfloat16, Hh)
    GETP(g_Wqkh, __nv_bfloat16, Wqkh)
    GETP(g_Wvh, __nv_bfloat16, Wvh)
    GETP(g_Woh, __nv_bfloat16, Woh)
    GETP(g_W1h, __nv_bfloat16, W1h)
    GETP(g_W2h, __nv_bfloat16, W2h)
    GETP(g_bqk, float, bqk)
    GETP(g_part, float2, part) GETP(g_stats, float2, stats)
#undef GETP

    cudaFuncSetAttribute(gemm_mma<true, false, false, 2>,
                         cudaFuncAttributeMaxDynamicSharedMemorySize, GEMM_DSMEM);
    cudaFuncSetAttribute(gemm_mma<true, true, false, 2>,
                         cudaFuncAttributeMaxDynamicSharedMemorySize, GEMM_DSMEM);
    cudaFuncSetAttribute(gemm_mma<true, false, true, 0>,
                         cudaFuncAttributeMaxDynamicSharedMemorySize, GEMM_DSMEM);

    // 0. weight conversion
    conv_all<<<3073, 256>>>(Wq, Wk, Wv, Wo, W1, W2, bq, bk);

    // 1. transpose + fp16 conversion
    dim3 trGrid(16, 2, Bn * Tn);
    dim3 trBlk(32, 8);
    prep_xr<<<trGrid, trBlk>>>(x, pe, XR, XRh, XPEh);

    // 2. fused Q+K projection, V projection (fp16 out)
    dim3 gQK(1024 / 128, MTOT / 256);
    gemm_mma<true, false, false, 2><<<gQK, 512, GEMM_DSMEM>>>(
        XPEh, Wqkh, bqk, nullptr, nullptr, QKh, 1024, Dn);
    dim3 gD(Dn / 128, MTOT / 256);
    gemm_mma<true, false, false, 2><<<gD, 512, GEMM_DSMEM>>>(
        XRh, Wvh, bv, nullptr, nullptr, Vmh, Dn, Dn);

    // 3. attention (tensor core)
    attn_tc<<<Bn * Hn, 256>>>(QKh, Vmh, adj, hw, ATTh);

    // 4. output projection + residual
    gemm_mma<true, false, true, 0><<<gD, 512, GEMM_DSMEM>>>(
        ATTh, Woh, bo, XR, Y1, nullptr, Dn, Dn);

    // 5. layernorm
    ln_partial<<<dim3(32, Bn), 256>>>(Y1, part);
    ln_final<<<1, 32>>>(part, stats);
    ln_apply<<<(MTOT * (size_t)Dn / 4) / 256, 256>>>(Y1, stats, g1, be1, X1, X1h);

    // 6. FFN
    dim3 gF1(FFn / 128, MTOT / 256);
    gemm_mma<true, true, false, 2><<<gF1, 512, GEMM_DSMEM>>>(
        X1h, W1h, b1, nullptr, nullptr, Hh, FFn, Dn);
    gemm_mma<true, false, true, 0><<<gD, 512, GEMM_DSMEM>>>(
        Hh, W2h, b2, X1, FFo, nullptr, Dn, FFn);

    // 7. output transpose
    out_tr<<<trGrid, trBlk>>>(FFo, out);
}

// round 15
// speedup vs baseline: 1.0537x; 1.0537x over previous
#include <cuda_runtime.h>
#include <cuda_bf16.h>
#include <cuda_fp16.h>
#include <cstdint>
#include <math.h>

#define Bn 32
#define Dn 512
#define Tn 32
#define Nn 64
#define Hn 8
#define DKn 64
#define FFn 2048
#define MTOT (Bn * Nn * Tn)
#define SCALE_F 0.022097086912079608f
#define LN_EPS 1e-5f

// ------------------------------------------------------------------
// Scratch. bf16-typed half buffers hold FP16 bits.
// ------------------------------------------------------------------
__device__ float g_XR[(size_t)MTOT * Dn];
__device__ float g_Y1[(size_t)MTOT * Dn];
__device__ float g_X1[(size_t)MTOT * Dn];
__device__ float g_FF[(size_t)MTOT * Dn];
__device__ __nv_bfloat16 g_QKh[(size_t)MTOT * 1024];    // fp16
__device__ __nv_bfloat16 g_Vmh[(size_t)MTOT * Dn];      // fp16
__device__ __nv_bfloat16 g_XRh[(size_t)MTOT * Dn];      // fp16
__device__ __nv_bfloat16 g_XPEh[(size_t)MTOT * Dn];     // fp16
__device__ __nv_bfloat16 g_ATTh[(size_t)MTOT * Dn];     // fp16
__device__ __nv_bfloat16 g_X1h[(size_t)MTOT * Dn];      // fp16
__device__ __nv_bfloat16 g_Hh[(size_t)MTOT * FFn];      // fp16
__device__ __nv_bfloat16 g_Wqkh[1024 * Dn];             // fp16
__device__ __nv_bfloat16 g_Wvh[Dn * Dn];                // fp16
__device__ __nv_bfloat16 g_Woh[Dn * Dn];                // fp16
__device__ __nv_bfloat16 g_W1h[FFn * Dn];               // fp16
__device__ __nv_bfloat16 g_W2h[Dn * FFn];               // fp16
__device__ float g_bqk[1024];
__device__ float2 g_part[Bn * 32];
__device__ float2 g_stats[Bn];

// ------------------------------------------------------------------
__device__ __forceinline__ uint32_t smem_u32(const void* p) {
    uint32_t a;
    asm("{ .reg .u64 t; cvta.to.shared.u64 t, %1; cvt.u32.u64 %0, t; }" : "=r"(a) : "l"(p));
    return a;
}
__device__ __forceinline__ void cpasync16(uint32_t dst, const void* src) {
    asm volatile("cp.async.cg.shared.global [%0], [%1], 16;" :: "r"(dst), "l"(src));
}
#define CP_COMMIT() asm volatile("cp.async.commit_group;" ::: "memory")
#define CP_WAIT0() asm volatile("cp.async.wait_group 0;" ::: "memory")

#define LDSM4(r0, r1, r2, r3, addr) \
    asm volatile("ldmatrix.sync.aligned.m8n8.x4.shared.b16 {%0,%1,%2,%3}, [%4];" \
                 : "=r"(r0), "=r"(r1), "=r"(r2), "=r"(r3) : "r"(addr))

#define LDSM4T(r0, r1, r2, r3, addr) \
    asm volatile("ldmatrix.sync.aligned.m8n8.x4.trans.shared.b16 {%0,%1,%2,%3}, [%4];" \
                 : "=r"(r0), "=r"(r1), "=r"(r2), "=r"(r3) : "r"(addr))

#define MMA_F16(d, a, b) \
    asm volatile("mma.sync.aligned.m16n8k16.row.col.f32.f16.f16.f32 " \
                 "{%0,%1,%2,%3}, {%4,%5,%6,%7}, {%8,%9}, {%0,%1,%2,%3};" \
                 : "+f"((d)[0]), "+f"((d)[1]), "+f"((d)[2]), "+f"((d)[3]) \
                 : "r"((a)[0]), "r"((a)[1]), "r"((a)[2]), "r"((a)[3]), \
                   "r"((b)[0]), "r"((b)[1]))

__device__ __forceinline__ uint32_t h2bits(float a, float b) {
    __half2 h = __floats2half2_rn(a, b);
    return *(uint32_t*)&h;
}

// ------------------------------------------------------------------
// weight conversion -> fp16; bias concat
// ------------------------------------------------------------------
__global__ void conv_all(const float* __restrict__ Wq, const float* __restrict__ Wk,
                         const float* __restrict__ Wv, const float* __restrict__ Wo,
                         const float* __restrict__ W1, const float* __restrict__ W2,
                         const float* __restrict__ bq, const float* __restrict__ bk) {
    long i4 = (long)blockIdx.x * 256 + threadIdx.x;
    if (i4 >= 786432) {
        int t = threadIdx.x;
        if (blockIdx.x == 3072) {
            g_bqk[t] = bq[t];
            g_bqk[t + 256] = bq[t + 256];
            g_bqk[t + 512] = bk[t];
            g_bqk[t + 768] = bk[t + 256];
        }
        return;
    }
    const float* src;
    __nv_bfloat16* dh;
    long o;
    if (i4 < 65536)       { src = Wq; dh = g_Wqkh;          o = i4; }
    else if (i4 < 131072) { src = Wk; dh = g_Wqkh + 262144; o = i4 - 65536; }
    else if (i4 < 196608) { src = Wv; dh = g_Wvh;           o = i4 - 131072; }
    else if (i4 < 262144) { src = Wo; dh = g_Woh;           o = i4 - 196608; }
    else if (i4 < 524288) { src = W1; dh = g_W1h;           o = i4 - 262144; }
    else                  { src = W2; dh = g_W2h;           o = i4 - 524288; }
    long e = o * 4;
    float4 v = *(const float4*)&src[e];
    *(uint2*)&dh[e] = make_uint2(h2bits(v.x, v.y), h2bits(v.z, v.w));
}

// ------------------------------------------------------------------
__global__ void prep_xr(const float* __restrict__ x, const float* __restrict__ pe,
                        float* __restrict__ XR,
                        __nv_bfloat16* __restrict__ XRh, __nv_bfloat16* __restrict__ XPEh) {
    __shared__ float tile[32][33];
    int bt = blockIdx.z;
    int b = bt >> 5, t = bt & 31;
    int d0 = blockIdx.x * 32, n0 = blockIdx.y * 32;
    size_t bbase = (size_t)b * (Dn * Tn * Nn);
#pragma unroll
    for (int i = 0; i < 4; i++) {
        int d = d0 + threadIdx.y + i * 8;
        tile[threadIdx.y + i * 8][threadIdx.x] =
            x[bbase + (size_t)d * (Tn * Nn) + t * Nn + n0 + threadIdx.x];
    }
    __syncthreads();
    int d = d0 + threadIdx.x;
#pragma unroll
    for (int i = 0; i < 4; i++) {
        int n = n0 + threadIdx.y + i * 8;
        float v = tile[threadIdx.x][threadIdx.y + i * 8];
        size_t idx = bbase + (size_t)n * (Tn * Dn) + t * Dn + d;
        XR[idx] = v;
        __half hv = __float2half_rn(v);
        *(uint16_t*)&XRh[idx] = *(uint16_t*)&hv;
        __half hp = __float2half_rn(v + pe[n * Dn + d]);
        *(uint16_t*)&XPEh[idx] = *(uint16_t*)&hp;
    }
}

__global__ void out_tr(const float* __restrict__ FF, float* __restrict__ out) {
    __shared__ float tile[32][33];
    int bt = blockIdx.z;
    int b = bt >> 5, t = bt & 31;
    int d0 = blockIdx.x * 32, n0 = blockIdx.y * 32;
    size_t bbase = (size_t)b * (Dn * Tn * Nn);
#pragma unroll
    for (int i = 0; i < 4; i++) {
        int n = n0 + threadIdx.y + i * 8;
        tile[threadIdx.y + i * 8][threadIdx.x] =
            FF[bbase + (size_t)n * (Tn * Dn) + t * Dn + d0 + threadIdx.x];
    }
    __syncthreads();
#pragma unroll
    for (int i = 0; i < 4; i++) {
        int d = d0 + threadIdx.y + i * 8;
        out[bbase + (size_t)d * (Tn * Nn) + t * Nn + n0 + threadIdx.x] =
            tile[threadIdx.x][threadIdx.y + i * 8];
    }
}

// ------------------------------------------------------------------
// fp16 GEMM: 256x128 tile, 256 threads, warp 64x64 (4x2), BK=128,
// 2-stage, 1 barrier/iter, pitch-272 smem, prefetch spread over 6 kc.
// OUTM_: 0=float, 2=fp16.  LNP_: fuse LayerNorm partial sums (Wo only).
// ------------------------------------------------------------------
#define PITCHB 272
#define STG_B (384 * PITCHB)            // 104448
#define GEMM_DSMEM (2 * STG_B)          // 208896

template <bool BIAS_, bool RELU_, bool RESID_, int OUTM_, bool LNP_>
__global__ void __launch_bounds__(256, 1)
gemm_mma(const __nv_bfloat16* __restrict__ Ah, const __nv_bfloat16* __restrict__ Wh,
         const float* __restrict__ bias, const float* __restrict__ Rsd,
         float* __restrict__ Cf, __nv_bfloat16* __restrict__ Ch,
         int Ncols, int K) {
    constexpr uint32_t oAH = 0;
    constexpr uint32_t oBH = 256 * PITCHB;

    extern __shared__ char smraw[];
    const uint32_t sb = smem_u32(smraw);
    const int tid = threadIdx.x;
    const int wid = tid >> 5;
    const int lane = tid & 31;
    const size_t rowBase = (size_t)blockIdx.y * 256;
    const int colBase = blockIdx.x * 128;
    const int wm = (wid >> 1) * 64;
    const int wn = (wid & 1) * 64;

    float acc[4][8][4];
#pragma unroll
    for (int mt = 0; mt < 4; mt++)
#pragma unroll
        for (int nt = 0; nt < 8; nt++)
#pragma unroll
            for (int q = 0; q < 4; q++) acc[mt][nt][q] = 0.f;

    const int KIT = K >> 7;

    auto load64 = [&](uint32_t sdst, const __nv_bfloat16* g, size_t row0, int k0, int r0) {
        const char* gbase = (const char*)(g + (row0 + r0) * (size_t)K + k0);
        size_t rs = (size_t)K * 2;
#pragma unroll
        for (int q = 0; q < 4; q++) {
            int ch = tid + q * 256;
            int r = ch >> 4, c = ch & 15;
            cpasync16(sdst + (r0 + r) * PITCHB + c * 16, gbase + (size_t)r * rs + c * 16);
        }
    };

#pragma unroll
    for (int r0 = 0; r0 < 256; r0 += 64) load64(sb + oAH, Ah, rowBase, 0, r0);
    load64(sb + oBH, Wh, (size_t)colBase, 0, 0);
    load64(sb + oBH, Wh, (size_t)colBase, 0, 64);
    CP_COMMIT();

    const int arow = lane & 15;
    const int ainc = lane >> 4;
    const int brow = (lane & 7) + ((lane >> 4) << 3);
    const int binc = (lane >> 3) & 1;

    for (int it = 0; it < KIT; ++it) {
        CP_WAIT0();
        __syncthreads();
        const bool pf = (it + 1 < KIT);
        const uint32_t stn = sb + ((it + 1) & 1) * STG_B;
        const int k0n = (it + 1) * 128;
        const uint32_t stb = sb + (it & 1) * STG_B;
#pragma unroll
        for (int kc = 0; kc < 8; kc++) {
            uint32_t ah[4][4], bh[8][2];
#pragma unroll
            for (int mt = 0; mt < 4; mt++) {
                uint32_t ad = stb + oAH + (wm + mt * 16 + arow) * PITCHB + kc * 32 + ainc * 16;
                LDSM4(ah[mt][0], ah[mt][1], ah[mt][2], ah[mt][3], ad);
            }
#pragma unroll
            for (int bt = 0; bt < 4; bt++) {
                uint32_t bd = stb + oBH + (wn + bt * 16 + brow) * PITCHB + kc * 32 + binc * 16;
                uint32_t r0, r1, r2, r3;
                LDSM4(r0, r1, r2, r3, bd);
                bh[2 * bt][0] = r0; bh[2 * bt][1] = r1;
                bh[2 * bt + 1][0] = r2; bh[2 * bt + 1][1] = r3;
            }
            if (pf) {
                if (kc < 4)       load64(stn + oAH, Ah, rowBase, k0n, kc * 64);
                else if (kc == 4) load64(stn + oBH, Wh, (size_t)colBase, k0n, 0);
                else if (kc == 5) load64(stn + oBH, Wh, (size_t)colBase, k0n, 64);
            }
#pragma unroll
            for (int mt = 0; mt < 4; mt++) {
#pragma unroll
                for (int nt = 0; nt < 8; nt++) {
                    MMA_F16(acc[mt][nt], ah[mt], bh[nt]);
                }
            }
        }
        CP_COMMIT();
    }

    // epilogue (+ optional fused LN partial sums)
    float lns = 0.f, lns2 = 0.f;
#pragma unroll
    for (int mt = 0; mt < 4; mt++) {
#pragma unroll
        for (int nt = 0; nt < 8; nt++) {
            const int col = colBase + wn + nt * 8 + (lane & 3) * 2;
#pragma unroll
            for (int half = 0; half < 2; half++) {
                const size_t row = rowBase + wm + mt * 16 + (lane >> 2) + half * 8;
                float vx = acc[mt][nt][half * 2 + 0];
                float vy = acc[mt][nt][half * 2 + 1];
                if (BIAS_) {
                    float2 bv = *(const float2*)&bias[col];
                    vx += bv.x; vy += bv.y;
                }
                if (RELU_) { vx = fmaxf(vx, 0.f); vy = fmaxf(vy, 0.f); }
                if (RESID_) {
                    float2 rv = *(const float2*)&Rsd[row * Ncols + col];
                    vx += rv.x; vy += rv.y;
                }
                if (LNP_) {
                    lns += vx + vy;
                    lns2 += vx * vx + vy * vy;
                }
                if (OUTM_ == 0) {
                    *(float2*)&Cf[row * Ncols + col] = make_float2(vx, vy);
                } else {
                    *(uint32_t*)&Ch[row * Ncols + col] = h2bits(vx, vy);
                }
            }
        }
    }

    if (LNP_) {
        __syncthreads();  // smem stages no longer needed; reuse for reduction
        float* rs = (float*)smraw;
        float* rs2 = rs + 256;
        rs[tid] = lns; rs2[tid] = lns2;
        __syncthreads();
        for (int o = 128; o; o >>= 1) {
            if (tid < o) {
                rs[tid] += rs[tid + o];
                rs2[tid] += rs2[tid + o];
            }
            __syncthreads();
        }
        if (tid == 0) {
            int pidx = ((int)blockIdx.y >> 3) * 32 + ((int)blockIdx.y & 7) * 4 + blockIdx.x;
            g_part[pidx] = make_float2(rs[0], rs2[0]);
        }
    }
}

// ------------------------------------------------------------------
// Tensor-core attention (R13)
// ------------------------------------------------------------------
#define AP 144
__global__ void __launch_bounds__(256)
attn_tc(const __nv_bfloat16* __restrict__ QKh, const __nv_bfloat16* __restrict__ Vmh,
        const float* __restrict__ adj, const float* __restrict__ hw,
        __nv_bfloat16* __restrict__ ATTh) {
    __shared__ __align__(16) char sQ[64 * AP];
    __shared__ __align__(16) char sK[64 * AP];
    __shared__ __align__(16) char sA[64 * AP];
    __shared__ float sS[64][68];

    const int b = blockIdx.x >> 3;
    const int h = blockIdx.x & 7;
    const int tid = threadIdx.x;
    const int wid = tid >> 5;
    const int lane = tid & 31;
    const int wm = (wid >> 1) * 16;
    const int wn = (wid & 1) * 32;
    const uint32_t uQ = smem_u32(sQ);
    const uint32_t uK = smem_u32(sK);
    const uint32_t uA = smem_u32(sA);

    const int arow = lane & 15;
    const int ainc = lane >> 4;
    const int brow = (lane & 7) + ((lane >> 4) << 3);
    const int binc = (lane >> 3) & 1;
    const int tkrow = (lane & 7) + (((lane >> 3) & 1) << 3);
    const int tncol = (lane >> 4) * 8;

    const size_t tokBase = (size_t)b * 2048;
    const int lr = tid >> 3;
    const int lc = tid & 7;

    float acc[4][4];
#pragma unroll
    for (int nt = 0; nt < 4; nt++)
#pragma unroll
        for (int q = 0; q < 4; q++) acc[nt][q] = 0.f;

    for (int t0 = 0; t0 < 32; t0++) {
        __syncthreads();
#pragma unroll
        for (int j = 0; j < 2; j++) {
            int r = lr + j * 32;
            const __nv_bfloat16* qsrc = QKh + (tokBase + r * 32 + t0) * 1024 + h * DKn;
            cpasync16(uQ + r * AP + lc * 16, (const char*)qsrc + lc * 16);
            cpasync16(uK + r * AP + lc * 16, (const char*)(qsrc + 512) + lc * 16);
        }
        CP_COMMIT();
        CP_WAIT0();
        __syncthreads();
#pragma unroll
        for (int kc = 0; kc < 4; kc++) {
            uint32_t a[4], bf[4][2];
            LDSM4(a[0], a[1], a[2], a[3], uQ + (wm + arow) * AP + kc * 32 + ainc * 16);
#pragma unroll
            for (int bt = 0; bt < 2; bt++) {
                uint32_t r0, r1, r2, r3;
                LDSM4(r0, r1, r2, r3, uK + (wn + bt * 16 + brow) * AP + kc * 32 + binc * 16);
                bf[2 * bt][0] = r0; bf[2 * bt][1] = r1;
                bf[2 * bt + 1][0] = r2; bf[2 * bt + 1][1] = r3;
            }
#pragma unroll
            for (int nt = 0; nt < 4; nt++) MMA_F16(acc[nt], a, bf[nt]);
        }
    }

    __syncthreads();
#pragma unroll
    for (int nt = 0; nt < 4; nt++) {
        int col = wn + nt * 8 + (lane & 3) * 2;
#pragma unroll
        for (int half = 0; half < 2; half++) {
            int row = wm + (lane >> 2) + half * 8;
            sS[row][col] = acc[nt][half * 2] * SCALE_F;
            sS[row][col + 1] = acc[nt][half * 2 + 1] * SCALE_F;
        }
    }
    __syncthreads();

    {
        const int w = wid, ln2 = lane;
        const float hwv = hw[h];
        for (int rr = 0; rr < 8; rr++) {
            int row = w * 8 + rr;
            float v0 = sS[row][ln2];
            float v1 = sS[row][ln2 + 32];
            float mx = fmaxf(v0, v1);
#pragma unroll
            for (int o = 16; o; o >>= 1) mx = fmaxf(mx, __shfl_xor_sync(0xffffffffu, mx, o));
            float e0 = __expf(v0 - mx), e1 = __expf(v1 - mx);
            float s = e0 + e1;
#pragma unroll
            for (int o = 16; o; o >>= 1) s += __shfl_xor_sync(0xffffffffu, s, o);
            float inv = 1.f / s;
            size_t ab = (size_t)h * 4096 + row * 64;
            sS[row][ln2]      = e0 * inv * hwv + adj[ab + ln2];
            sS[row][ln2 + 32] = e1 * inv * hwv + adj[ab + 32 + ln2];
        }
    }
    __syncthreads();

    {
        int q = tid >> 2, mb = (tid & 3) * 16;
#pragma unroll
        for (int m = 0; m < 16; m += 2) {
            *(uint32_t*)(sA + q * AP + (mb + m) * 2) = h2bits(sS[q][mb + m], sS[q][mb + m + 1]);
        }
    }

    for (int t0 = 0; t0 < 32; t0++) {
        __syncthreads();
#pragma unroll
        for (int j = 0; j < 2; j++) {
            int r = lr + j * 32;
            const __nv_bfloat16* vsrc = Vmh + (tokBase + r * 32 + t0) * 512 + h * DKn;
            cpasync16(uK + r * AP + lc * 16, (const char*)vsrc + lc * 16);
        }
        CP_COMMIT();
        CP_WAIT0();
        __syncthreads();
        float o2[4][4];
#pragma unroll
        for (int nt = 0; nt < 4; nt++)
#pragma unroll
            for (int q = 0; q < 4; q++) o2[nt][q] = 0.f;
#pragma unroll
        for (int kc = 0; kc < 4; kc++) {
            uint32_t a[4], bf[4][2];
            LDSM4(a[0], a[1], a[2], a[3], uA + (wm + arow) * AP + kc * 32 + ainc * 16);
#pragma unroll
            for (int bt = 0; bt < 2; bt++) {
                uint32_t r0, r1, r2, r3;
                LDSM4T(r0, r1, r2, r3,
                       uK + (kc * 16 + tkrow) * AP + (wn + bt * 16 + tncol) * 2);
                bf[2 * bt][0] = r0; bf[2 * bt][1] = r1;
                bf[2 * bt + 1][0] = r2; bf[2 * bt + 1][1] = r3;
            }
#pragma unroll
            for (int nt = 0; nt < 4; nt++) MMA_F16(o2[nt], a, bf[nt]);
        }
#pragma unroll
        for (int nt = 0; nt < 4; nt++) {
            int dk = wn + nt * 8 + (lane & 3) * 2;
#pragma unroll
            for (int half = 0; half < 2; half++) {
                int qrow = wm + (lane >> 2) + half * 8;
                size_t off = (tokBase + qrow * 32 + t0) * 512 + h * DKn + dk;
                *(uint32_t*)&ATTh[off] = h2bits(o2[nt][half * 2], o2[nt][half * 2 + 1]);
            }
        }
    }
}

// ------------------------------------------------------------------
// LayerNorm (partial now fused into Wo epilogue)
// ------------------------------------------------------------------
__global__ void ln_final(const float2* __restrict__ part, float2* __restrict__ stats) {
    int b = threadIdx.x;
    if (b < Bn) {
        float s = 0.f, s2 = 0.f;
        for (int c = 0; c < 32; c++) {
            float2 p = part[b * 32 + c];
            s += p.x; s2 += p.y;
        }
        const float invN = 1.0f / 1048576.0f;
        float mean = s * invN;
        float var = s2 * invN - mean * mean;
        stats[b] = make_float2(mean, rsqrtf(var + LN_EPS));
    }
}

__global__ void ln_apply(const float* __restrict__ Y1, const float2* __restrict__ stats,
                         const float* __restrict__ g1, const float* __restrict__ be1,
                         float* __restrict__ X1, __nv_bfloat16* __restrict__ X1h) {
    size_t e = ((size_t)blockIdx.x * blockDim.x + threadIdx.x) * 4;
    float2 st = stats[e >> 20];
    size_t gi = e & 1048575;
    float4 y = *(const float4*)&Y1[e];
    float4 g = *(const float4*)&g1[gi];
    float4 be = *(const float4*)&be1[gi];
    float4 o;
    o.x = (y.x - st.x) * st.y * g.x + be.x;
    o.y = (y.y - st.x) * st.y * g.y + be.y;
    o.z = (y.z - st.x) * st.y * g.z + be.z;
    o.w = (y.w - st.x) * st.y * g.w + be.w;
    *(float4*)&X1[e] = o;
    *(uint2*)&X1h[e] = make_uint2(h2bits(o.x, o.y), h2bits(o.z, o.w));
}

// ------------------------------------------------------------------
extern "C" void kernel_launch(void* const* d_in, const int* in_sizes, int n_in,
                              void* d_out, int out_size) {
    const float* x   = (const float*)d_in[0];
    const float* Wq  = (const float*)d_in[1];
    const float* bq  = (const float*)d_in[2];
    const float* Wk  = (const float*)d_in[3];
    const float* bk  = (const float*)d_in[4];
    const float* Wv  = (const float*)d_in[5];
    const float* bv  = (const float*)d_in[6];
    const float* Wo  = (const float*)d_in[7];
    const float* bo  = (const float*)d_in[8];
    const float* W1  = (const float*)d_in[9];
    const float* b1  = (const float*)d_in[10];
    const float* W2  = (const float*)d_in[11];
    const float* b2  = (const float*)d_in[12];
    const float* g1  = (const float*)d_in[13];
    const float* be1 = (const float*)d_in[14];
    const float* adj = (const float*)d_in[15];
    const float* hw  = (const float*)d_in[16];
    const float* pe  = (const float*)d_in[17];
    float* out = (float*)d_out;

#define GETP(sym, ty, name) ty* name; { void* _p; cudaGetSymbolAddress(&_p, sym); name = (ty*)_p; }
    GETP(g_XR, float, XR) GETP(g_Y1, float, Y1) GETP(g_X1, float, X1) GETP(g_FF, float, FFo)
    GETP(g_QKh, __nv_bfloat16, QKh)
    GETP(g_Vmh, __nv_bfloat16, Vmh)
    GETP(g_XRh, __nv_bfloat16, XRh)
    GETP(g_XPEh, __nv_bfloat16, XPEh)
    GETP(g_ATTh, __nv_bfloat16, ATTh)
    GETP(g_X1h, __nv_bfloat16, X1h)
    GETP(g_Hh, __nv_bfloat16, Hh)
    GETP(g_Wqkh, __nv_bfloat16, Wqkh)
    GETP(g_Wvh, __nv_bfloat16, Wvh)
    GETP(g_Woh, __nv_bfloat16, Woh)
    GETP(g_W1h, __nv_bfloat16, W1h)
    GETP(g_W2h, __nv_bfloat16, W2h)
    GETP(g_bqk, float, bqk)
    GETP(g_part, float2, part) GETP(g_stats, float2, stats)
#undef GETP

    cudaFuncSetAttribute(gemm_mma<true, false, false, 2, false>,
                         cudaFuncAttributeMaxDynamicSharedMemorySize, GEMM_DSMEM);
    cudaFuncSetAttribute(gemm_mma<true, true, false, 2, false>,
                         cudaFuncAttributeMaxDynamicSharedMemorySize, GEMM_DSMEM);
    cudaFuncSetAttribute(gemm_mma<true, false, true, 0, true>,
                         cudaFuncAttributeMaxDynamicSharedMemorySize, GEMM_DSMEM);
    cudaFuncSetAttribute(gemm_mma<true, false, true, 0, false>,
                         cudaFuncAttributeMaxDynamicSharedMemorySize, GEMM_DSMEM);

    // 0. weight conversion
    conv_all<<<3073, 256>>>(Wq, Wk, Wv, Wo, W1, W2, bq, bk);

    // 1. transpose + fp16 conversion
    dim3 trGrid(16, 2, Bn * Tn);
    dim3 trBlk(32, 8);
    prep_xr<<<trGrid, trBlk>>>(x, pe, XR, XRh, XPEh);

    // 2. fused Q+K projection, V projection (fp16 out)
    dim3 gQK(1024 / 128, MTOT / 256);
    gemm_mma<true, false, false, 2, false><<<gQK, 256, GEMM_DSMEM>>>(
        XPEh, Wqkh, bqk, nullptr, nullptr, QKh, 1024, Dn);
    dim3 gD(Dn / 128, MTOT / 256);
    gemm_mma<true, false, false, 2, false><<<gD, 256, GEMM_DSMEM>>>(
        XRh, Wvh, bv, nullptr, nullptr, Vmh, Dn, Dn);

    // 3. attention (tensor core)
    attn_tc<<<Bn * Hn, 256>>>(QKh, Vmh, adj, hw, ATTh);

    // 4. output projection + residual + fused LN partial sums
    gemm_mma<true, false, true, 0, true><<<gD, 256, GEMM_DSMEM>>>(
        ATTh, Woh, bo, XR, Y1, nullptr, Dn, Dn);

    // 5. layernorm (partials already in g_part)
    ln_final<<<1, 32>>>(part, stats);
    ln_apply<<<(MTOT * (size_t)Dn / 4) / 256, 256>>>(Y1, stats, g1, be1, X1, X1h);

    // 6. FFN
    dim3 gF1(FFn / 128, MTOT / 256);
    gemm_mma<true, true, false, 2, false><<<gF1, 256, GEMM_DSMEM>>>(
        X1h, W1h, b1, nullptr, nullptr, Hh, FFn, Dn);
    gemm_mma<true, false, true, 0, false><<<gD, 256, GEMM_DSMEM>>>(
        Hh, W2h, b2, X1, FFo, nullptr, Dn, FFn);

    // 7. output transpose
    out_tr<<<trGrid, trBlk>>>(FFo, out);
}

// round 16
// speedup vs baseline: 1.0775x; 1.0226x over previous
#include <cuda_runtime.h>
#include <cuda_bf16.h>
#include <cuda_fp16.h>
#include <cstdint>
#include <math.h>

#define Bn 32
#define Dn 512
#define Tn 32
#define Nn 64
#define Hn 8
#define DKn 64
#define FFn 2048
#define MTOT (Bn * Nn * Tn)
#define SCALE_F 0.022097086912079608f
#define LN_EPS 1e-5f

// ------------------------------------------------------------------
// Scratch. bf16-typed half buffers hold FP16 bits.
// ------------------------------------------------------------------
__device__ float g_XR[(size_t)MTOT * Dn];
__device__ float g_Y1[(size_t)MTOT * Dn];
__device__ __nv_bfloat16 g_QKh[(size_t)MTOT * 1024];    // fp16
__device__ __nv_bfloat16 g_Vmh[(size_t)MTOT * Dn];      // fp16
__device__ __nv_bfloat16 g_XRh[(size_t)MTOT * Dn];      // fp16
__device__ __nv_bfloat16 g_XPEh[(size_t)MTOT * Dn];     // fp16
__device__ __nv_bfloat16 g_ATTh[(size_t)MTOT * Dn];     // fp16
__device__ __nv_bfloat16 g_X1h[(size_t)MTOT * Dn];      // fp16
__device__ __nv_bfloat16 g_Hh[(size_t)MTOT * FFn];      // fp16
__device__ __nv_bfloat16 g_Wqkh[1024 * Dn];             // fp16
__device__ __nv_bfloat16 g_Wvh[Dn * Dn];                // fp16
__device__ __nv_bfloat16 g_Woh[Dn * Dn];                // fp16
__device__ __nv_bfloat16 g_W1h[FFn * Dn];               // fp16
__device__ __nv_bfloat16 g_W2h[Dn * FFn];               // fp16
__device__ float g_bqk[1024];
__device__ float2 g_part[Bn * 32];
__device__ float2 g_stats[Bn];

// ------------------------------------------------------------------
__device__ __forceinline__ uint32_t smem_u32(const void* p) {
    uint32_t a;
    asm("{ .reg .u64 t; cvta.to.shared.u64 t, %1; cvt.u32.u64 %0, t; }" : "=r"(a) : "l"(p));
    return a;
}
__device__ __forceinline__ void cpasync16(uint32_t dst, const void* src) {
    asm volatile("cp.async.cg.shared.global [%0], [%1], 16;" :: "r"(dst), "l"(src));
}
#define CP_COMMIT() asm volatile("cp.async.commit_group;" ::: "memory")
#define CP_WAIT0() asm volatile("cp.async.wait_group 0;" ::: "memory")

#define LDSM4(r0, r1, r2, r3, addr) \
    asm volatile("ldmatrix.sync.aligned.m8n8.x4.shared.b16 {%0,%1,%2,%3}, [%4];" \
                 : "=r"(r0), "=r"(r1), "=r"(r2), "=r"(r3) : "r"(addr))

#define LDSM4T(r0, r1, r2, r3, addr) \
    asm volatile("ldmatrix.sync.aligned.m8n8.x4.trans.shared.b16 {%0,%1,%2,%3}, [%4];" \
                 : "=r"(r0), "=r"(r1), "=r"(r2), "=r"(r3) : "r"(addr))

#define MMA_F16(d, a, b) \
    asm volatile("mma.sync.aligned.m16n8k16.row.col.f32.f16.f16.f32 " \
                 "{%0,%1,%2,%3}, {%4,%5,%6,%7}, {%8,%9}, {%0,%1,%2,%3};" \
                 : "+f"((d)[0]), "+f"((d)[1]), "+f"((d)[2]), "+f"((d)[3]) \
                 : "r"((a)[0]), "r"((a)[1]), "r"((a)[2]), "r"((a)[3]), \
                   "r"((b)[0]), "r"((b)[1]))

__device__ __forceinline__ uint32_t h2bits(float a, float b) {
    __half2 h = __floats2half2_rn(a, b);
    return *(uint32_t*)&h;
}

// ------------------------------------------------------------------
// weight conversion -> fp16; bias concat
// ------------------------------------------------------------------
__global__ void conv_all(const float* __restrict__ Wq, const float* __restrict__ Wk,
                         const float* __restrict__ Wv, const float* __restrict__ Wo,
                         const float* __restrict__ W1, const float* __restrict__ W2,
                         const float* __restrict__ bq, const float* __restrict__ bk) {
    long i4 = (long)blockIdx.x * 256 + threadIdx.x;
    if (i4 >= 786432) {
        int t = threadIdx.x;
        if (blockIdx.x == 3072) {
            g_bqk[t] = bq[t];
            g_bqk[t + 256] = bq[t + 256];
            g_bqk[t + 512] = bk[t];
            g_bqk[t + 768] = bk[t + 256];
        }
        return;
    }
    const float* src;
    __nv_bfloat16* dh;
    long o;
    if (i4 < 65536)       { src = Wq; dh = g_Wqkh;          o = i4; }
    else if (i4 < 131072) { src = Wk; dh = g_Wqkh + 262144; o = i4 - 65536; }
    else if (i4 < 196608) { src = Wv; dh = g_Wvh;           o = i4 - 131072; }
    else if (i4 < 262144) { src = Wo; dh = g_Woh;           o = i4 - 196608; }
    else if (i4 < 524288) { src = W1; dh = g_W1h;           o = i4 - 262144; }
    else                  { src = W2; dh = g_W2h;           o = i4 - 524288; }
    long e = o * 4;
    float4 v = *(const float4*)&src[e];
    *(uint2*)&dh[e] = make_uint2(h2bits(v.x, v.y), h2bits(v.z, v.w));
}

// ------------------------------------------------------------------
__global__ void prep_xr(const float* __restrict__ x, const float* __restrict__ pe,
                        float* __restrict__ XR,
                        __nv_bfloat16* __restrict__ XRh, __nv_bfloat16* __restrict__ XPEh) {
    __shared__ float tile[32][33];
    int bt = blockIdx.z;
    int b = bt >> 5, t = bt & 31;
    int d0 = blockIdx.x * 32, n0 = blockIdx.y * 32;
    size_t bbase = (size_t)b * (Dn * Tn * Nn);
#pragma unroll
    for (int i = 0; i < 4; i++) {
        int d = d0 + threadIdx.y + i * 8;
        tile[threadIdx.y + i * 8][threadIdx.x] =
            x[bbase + (size_t)d * (Tn * Nn) + t * Nn + n0 + threadIdx.x];
    }
    __syncthreads();
    int d = d0 + threadIdx.x;
#pragma unroll
    for (int i = 0; i < 4; i++) {
        int n = n0 + threadIdx.y + i * 8;
        float v = tile[threadIdx.x][threadIdx.y + i * 8];
        size_t idx = bbase + (size_t)n * (Tn * Dn) + t * Dn + d;
        XR[idx] = v;
        __half hv = __float2half_rn(v);
        *(uint16_t*)&XRh[idx] = *(uint16_t*)&hv;
        __half hp = __float2half_rn(v + pe[n * Dn + d]);
        *(uint16_t*)&XPEh[idx] = *(uint16_t*)&hp;
    }
}

// ------------------------------------------------------------------
// fp16 GEMM: 256x128 tile, 256 threads, warp 64x64 (4x2), BK=128,
// 2-stage, 1 barrier/iter, pitch-272 smem, prefetch spread over 6 kc.
// OUTM_: 0=float, 2=fp16, 3=direct-transposed output (B,D,T,N).
// RESID_: fp32 residual. RESH_: fp16 residual. LNP_: fused LN partials.
// ------------------------------------------------------------------
#define PITCHB 272
#define STG_B (384 * PITCHB)            // 104448
#define GEMM_DSMEM (2 * STG_B)          // 208896
#define TPITCH 260                      // fp32 transpose staging pitch

template <bool BIAS_, bool RELU_, bool RESID_, bool RESH_, int OUTM_, bool LNP_>
__global__ void __launch_bounds__(256, 1)
gemm_mma(const __nv_bfloat16* __restrict__ Ah, const __nv_bfloat16* __restrict__ Wh,
         const float* __restrict__ bias, const float* __restrict__ Rsd,
         const __nv_bfloat16* __restrict__ RsdH,
         float* __restrict__ Cf, __nv_bfloat16* __restrict__ Ch,
         int Ncols, int K) {
    constexpr uint32_t oAH = 0;
    constexpr uint32_t oBH = 256 * PITCHB;

    extern __shared__ char smraw[];
    const uint32_t sb = smem_u32(smraw);
    const int tid = threadIdx.x;
    const int wid = tid >> 5;
    const int lane = tid & 31;
    const size_t rowBase = (size_t)blockIdx.y * 256;
    const int colBase = blockIdx.x * 128;
    const int wm = (wid >> 1) * 64;
    const int wn = (wid & 1) * 64;

    float acc[4][8][4];
#pragma unroll
    for (int mt = 0; mt < 4; mt++)
#pragma unroll
        for (int nt = 0; nt < 8; nt++)
#pragma unroll
            for (int q = 0; q < 4; q++) acc[mt][nt][q] = 0.f;

    const int KIT = K >> 7;

    auto load64 = [&](uint32_t sdst, const __nv_bfloat16* g, size_t row0, int k0, int r0) {
        const char* gbase = (const char*)(g + (row0 + r0) * (size_t)K + k0);
        size_t rs = (size_t)K * 2;
#pragma unroll
        for (int q = 0; q < 4; q++) {
            int ch = tid + q * 256;
            int r = ch >> 4, c = ch & 15;
            cpasync16(sdst + (r0 + r) * PITCHB + c * 16, gbase + (size_t)r * rs + c * 16);
        }
    };

#pragma unroll
    for (int r0 = 0; r0 < 256; r0 += 64) load64(sb + oAH, Ah, rowBase, 0, r0);
    load64(sb + oBH, Wh, (size_t)colBase, 0, 0);
    load64(sb + oBH, Wh, (size_t)colBase, 0, 64);
    CP_COMMIT();

    const int arow = lane & 15;
    const int ainc = lane >> 4;
    const int brow = (lane & 7) + ((lane >> 4) << 3);
    const int binc = (lane >> 3) & 1;

    for (int it = 0; it < KIT; ++it) {
        CP_WAIT0();
        __syncthreads();
        const bool pf = (it + 1 < KIT);
        const uint32_t stn = sb + ((it + 1) & 1) * STG_B;
        const int k0n = (it + 1) * 128;
        const uint32_t stb = sb + (it & 1) * STG_B;
#pragma unroll
        for (int kc = 0; kc < 8; kc++) {
            uint32_t ah[4][4], bh[8][2];
#pragma unroll
            for (int mt = 0; mt < 4; mt++) {
                uint32_t ad = stb + oAH + (wm + mt * 16 + arow) * PITCHB + kc * 32 + ainc * 16;
                LDSM4(ah[mt][0], ah[mt][1], ah[mt][2], ah[mt][3], ad);
            }
#pragma unroll
            for (int bt = 0; bt < 4; bt++) {
                uint32_t bd = stb + oBH + (wn + bt * 16 + brow) * PITCHB + kc * 32 + binc * 16;
                uint32_t r0, r1, r2, r3;
                LDSM4(r0, r1, r2, r3, bd);
                bh[2 * bt][0] = r0; bh[2 * bt][1] = r1;
                bh[2 * bt + 1][0] = r2; bh[2 * bt + 1][1] = r3;
            }
            if (pf) {
                if (kc < 4)       load64(stn + oAH, Ah, rowBase, k0n, kc * 64);
                else if (kc == 4) load64(stn + oBH, Wh, (size_t)colBase, k0n, 0);
                else if (kc == 5) load64(stn + oBH, Wh, (size_t)colBase, k0n, 64);
            }
#pragma unroll
            for (int mt = 0; mt < 4; mt++) {
#pragma unroll
                for (int nt = 0; nt < 8; nt++) {
                    MMA_F16(acc[mt][nt], ah[mt], bh[nt]);
                }
            }
        }
        CP_COMMIT();
    }

    float* sT = (float*)smraw;     // transpose staging (OUTM_==3)
    if (OUTM_ == 3) __syncthreads();  // all warps done reading stage smem

    // epilogue (+ optional fused LN partial sums)
    float lns = 0.f, lns2 = 0.f;
#pragma unroll
    for (int mt = 0; mt < 4; mt++) {
#pragma unroll
        for (int nt = 0; nt < 8; nt++) {
            const int colL = wn + nt * 8 + (lane & 3) * 2;
            const int col = colBase + colL;
#pragma unroll
            for (int half = 0; half < 2; half++) {
                const int rowL = wm + mt * 16 + (lane >> 2) + half * 8;
                const size_t row = rowBase + rowL;
                float vx = acc[mt][nt][half * 2 + 0];
                float vy = acc[mt][nt][half * 2 + 1];
                if (BIAS_) {
                    float2 bv = *(const float2*)&bias[col];
                    vx += bv.x; vy += bv.y;
                }
                if (RELU_) { vx = fmaxf(vx, 0.f); vy = fmaxf(vy, 0.f); }
                if (RESID_) {
                    float2 rv = *(const float2*)&Rsd[row * Ncols + col];
                    vx += rv.x; vy += rv.y;
                }
                if (RESH_) {
                    __half2 rh = *(const __half2*)&RsdH[row * Ncols + col];
                    vx += __low2float(rh); vy += __high2float(rh);
                }
                if (LNP_) {
                    lns += vx + vy;
                    lns2 += vx * vx + vy * vy;
                }
                if (OUTM_ == 0) {
                    *(float2*)&Cf[row * Ncols + col] = make_float2(vx, vy);
                } else if (OUTM_ == 2) {
                    *(uint32_t*)&Ch[row * Ncols + col] = h2bits(vx, vy);
                } else {  // OUTM_==3: stage to smem transposed
                    sT[colL * TPITCH + rowL] = vx;
                    sT[(colL + 1) * TPITCH + rowL] = vy;
                }
            }
        }
    }

    if (OUTM_ == 3) {
        __syncthreads();
        const int b = (int)blockIdx.y >> 3;
        const int nb = ((int)blockIdx.y & 7) * 8;
#pragma unroll
        for (int p = 0; p < 16; p++) {
            int idx = p * 256 + tid;
            int d = idx >> 5, t = idx & 31;
            float v[8];
#pragma unroll
            for (int nl = 0; nl < 8; nl++) v[nl] = sT[d * TPITCH + nl * 32 + t];
            size_t o = (((size_t)(b * Dn + colBase + d) * Tn) + t) * Nn + nb;
            *(float4*)&Cf[o] = make_float4(v[0], v[1], v[2], v[3]);
            *(float4*)&Cf[o + 4] = make_float4(v[4], v[5], v[6], v[7]);
        }
    }

    if (LNP_) {
        __syncthreads();
        float* rs = (float*)smraw;
        float* rs2 = rs + 256;
        rs[tid] = lns; rs2[tid] = lns2;
        __syncthreads();
        for (int o = 128; o; o >>= 1) {
            if (tid < o) {
                rs[tid] += rs[tid + o];
                rs2[tid] += rs2[tid + o];
            }
            __syncthreads();
        }
        if (tid == 0) {
            int pidx = ((int)blockIdx.y >> 3) * 32 + ((int)blockIdx.y & 7) * 4 + blockIdx.x;
            g_part[pidx] = make_float2(rs[0], rs2[0]);
        }
    }
}

// ------------------------------------------------------------------
// Tensor-core attention (R13)
// ------------------------------------------------------------------
#define AP 144
__global__ void __launch_bounds__(256)
attn_tc(const __nv_bfloat16* __restrict__ QKh, const __nv_bfloat16* __restrict__ Vmh,
        const float* __restrict__ adj, const float* __restrict__ hw,
        __nv_bfloat16* __restrict__ ATTh) {
    __shared__ __align__(16) char sQ[64 * AP];
    __shared__ __align__(16) char sK[64 * AP];
    __shared__ __align__(16) char sA[64 * AP];
    __shared__ float sS[64][68];

    const int b = blockIdx.x >> 3;
    const int h = blockIdx.x & 7;
    const int tid = threadIdx.x;
    const int wid = tid >> 5;
    const int lane = tid & 31;
    const int wm = (wid >> 1) * 16;
    const int wn = (wid & 1) * 32;
    const uint32_t uQ = smem_u32(sQ);
    const uint32_t uK = smem_u32(sK);
    const uint32_t uA = smem_u32(sA);

    const int arow = lane & 15;
    const int ainc = lane >> 4;
    const int brow = (lane & 7) + ((lane >> 4) << 3);
    const int binc = (lane >> 3) & 1;
    const int tkrow = (lane & 7) + (((lane >> 3) & 1) << 3);
    const int tncol = (lane >> 4) * 8;

    const size_t tokBase = (size_t)b * 2048;
    const int lr = tid >> 3;
    const int lc = tid & 7;

    float acc[4][4];
#pragma unroll
    for (int nt = 0; nt < 4; nt++)
#pragma unroll
        for (int q = 0; q < 4; q++) acc[nt][q] = 0.f;

    for (int t0 = 0; t0 < 32; t0++) {
        __syncthreads();
#pragma unroll
        for (int j = 0; j < 2; j++) {
            int r = lr + j * 32;
            const __nv_bfloat16* qsrc = QKh + (tokBase + r * 32 + t0) * 1024 + h * DKn;
            cpasync16(uQ + r * AP + lc * 16, (const char*)qsrc + lc * 16);
            cpasync16(uK + r * AP + lc * 16, (const char*)(qsrc + 512) + lc * 16);
        }
        CP_COMMIT();
        CP_WAIT0();
        __syncthreads();
#pragma unroll
        for (int kc = 0; kc < 4; kc++) {
            uint32_t a[4], bf[4][2];
            LDSM4(a[0], a[1], a[2], a[3], uQ + (wm + arow) * AP + kc * 32 + ainc * 16);
#pragma unroll
            for (int bt = 0; bt < 2; bt++) {
                uint32_t r0, r1, r2, r3;
                LDSM4(r0, r1, r2, r3, uK + (wn + bt * 16 + brow) * AP + kc * 32 + binc * 16);
                bf[2 * bt][0] = r0; bf[2 * bt][1] = r1;
                bf[2 * bt + 1][0] = r2; bf[2 * bt + 1][1] = r3;
            }
#pragma unroll
            for (int nt = 0; nt < 4; nt++) MMA_F16(acc[nt], a, bf[nt]);
        }
    }

    __syncthreads();
#pragma unroll
    for (int nt = 0; nt < 4; nt++) {
        int col = wn + nt * 8 + (lane & 3) * 2;
#pragma unroll
        for (int half = 0; half < 2; half++) {
            int row = wm + (lane >> 2) + half * 8;
            sS[row][col] = acc[nt][half * 2] * SCALE_F;
            sS[row][col + 1] = acc[nt][half * 2 + 1] * SCALE_F;
        }
    }
    __syncthreads();

    {
        const int w = wid, ln2 = lane;
        const float hwv = hw[h];
        for (int rr = 0; rr < 8; rr++) {
            int row = w * 8 + rr;
            float v0 = sS[row][ln2];
            float v1 = sS[row][ln2 + 32];
            float mx = fmaxf(v0, v1);
#pragma unroll
            for (int o = 16; o; o >>= 1) mx = fmaxf(mx, __shfl_xor_sync(0xffffffffu, mx, o));
            float e0 = __expf(v0 - mx), e1 = __expf(v1 - mx);
            float s = e0 + e1;
#pragma unroll
            for (int o = 16; o; o >>= 1) s += __shfl_xor_sync(0xffffffffu, s, o);
            float inv = 1.f / s;
            size_t ab = (size_t)h * 4096 + row * 64;
            sS[row][ln2]      = e0 * inv * hwv + adj[ab + ln2];
            sS[row][ln2 + 32] = e1 * inv * hwv + adj[ab + 32 + ln2];
        }
    }
    __syncthreads();

    {
        int q = tid >> 2, mb = (tid & 3) * 16;
#pragma unroll
        for (int m = 0; m < 16; m += 2) {
            *(uint32_t*)(sA + q * AP + (mb + m) * 2) = h2bits(sS[q][mb + m], sS[q][mb + m + 1]);
        }
    }

    for (int t0 = 0; t0 < 32; t0++) {
        __syncthreads();
#pragma unroll
        for (int j = 0; j < 2; j++) {
            int r = lr + j * 32;
            const __nv_bfloat16* vsrc = Vmh + (tokBase + r * 32 + t0) * 512 + h * DKn;
            cpasync16(uK + r * AP + lc * 16, (const char*)vsrc + lc * 16);
        }
        CP_COMMIT();
        CP_WAIT0();
        __syncthreads();
        float o2[4][4];
#pragma unroll
        for (int nt = 0; nt < 4; nt++)
#pragma unroll
            for (int q = 0; q < 4; q++) o2[nt][q] = 0.f;
#pragma unroll
        for (int kc = 0; kc < 4; kc++) {
            uint32_t a[4], bf[4][2];
            LDSM4(a[0], a[1], a[2], a[3], uA + (wm + arow) * AP + kc * 32 + ainc * 16);
#pragma unroll
            for (int bt = 0; bt < 2; bt++) {
                uint32_t r0, r1, r2, r3;
                LDSM4T(r0, r1, r2, r3,
                       uK + (kc * 16 + tkrow) * AP + (wn + bt * 16 + tncol) * 2);
                bf[2 * bt][0] = r0; bf[2 * bt][1] = r1;
                bf[2 * bt + 1][0] = r2; bf[2 * bt + 1][1] = r3;
            }
#pragma unroll
            for (int nt = 0; nt < 4; nt++) MMA_F16(o2[nt], a, bf[nt]);
        }
#pragma unroll
        for (int nt = 0; nt < 4; nt++) {
            int dk = wn + nt * 8 + (lane & 3) * 2;
#pragma unroll
            for (int half = 0; half < 2; half++) {
                int qrow = wm + (lane >> 2) + half * 8;
                size_t off = (tokBase + qrow * 32 + t0) * 512 + h * DKn + dk;
                *(uint32_t*)&ATTh[off] = h2bits(o2[nt][half * 2], o2[nt][half * 2 + 1]);
            }
        }
    }
}

// ------------------------------------------------------------------
// LayerNorm (partials fused into Wo epilogue)
// ------------------------------------------------------------------
__global__ void ln_final(const float2* __restrict__ part, float2* __restrict__ stats) {
    int b = threadIdx.x;
    if (b < Bn) {
        float s = 0.f, s2 = 0.f;
        for (int c = 0; c < 32; c++) {
            float2 p = part[b * 32 + c];
            s += p.x; s2 += p.y;
        }
        const float invN = 1.0f / 1048576.0f;
        float mean = s * invN;
        float var = s2 * invN - mean * mean;
        stats[b] = make_float2(mean, rsqrtf(var + LN_EPS));
    }
}

__global__ void ln_apply(const float* __restrict__ Y1, const float2* __restrict__ stats,
                         const float* __restrict__ g1, const float* __restrict__ be1,
                         __nv_bfloat16* __restrict__ X1h) {
    size_t e = ((size_t)blockIdx.x * blockDim.x + threadIdx.x) * 4;
    float2 st = stats[e >> 20];
    size_t gi = e & 1048575;
    float4 y = *(const float4*)&Y1[e];
    float4 g = *(const float4*)&g1[gi];
    float4 be = *(const float4*)&be1[gi];
    float4 o;
    o.x = (y.x - st.x) * st.y * g.x + be.x;
    o.y = (y.y - st.x) * st.y * g.y + be.y;
    o.z = (y.z - st.x) * st.y * g.z + be.z;
    o.w = (y.w - st.x) * st.y * g.w + be.w;
    *(uint2*)&X1h[e] = make_uint2(h2bits(o.x, o.y), h2bits(o.z, o.w));
}

// ------------------------------------------------------------------
extern "C" void kernel_launch(void* const* d_in, const int* in_sizes, int n_in,
                              void* d_out, int out_size) {
    const float* x   = (const float*)d_in[0];
    const float* Wq  = (const float*)d_in[1];
    const float* bq  = (const float*)d_in[2];
    const float* Wk  = (const float*)d_in[3];
    const float* bk  = (const float*)d_in[4];
    const float* Wv  = (const float*)d_in[5];
    const float* bv  = (const float*)d_in[6];
    const float* Wo  = (const float*)d_in[7];
    const float* bo  = (const float*)d_in[8];
    const float* W1  = (const float*)d_in[9];
    const float* b1  = (const float*)d_in[10];
    const float* W2  = (const float*)d_in[11];
    const float* b2  = (const float*)d_in[12];
    const float* g1  = (const float*)d_in[13];
    const float* be1 = (const float*)d_in[14];
    const float* adj = (const float*)d_in[15];
    const float* hw  = (const float*)d_in[16];
    const float* pe  = (const float*)d_in[17];
    float* out = (float*)d_out;

#define GETP(sym, ty, name) ty* name; { void* _p; cudaGetSymbolAddress(&_p, sym); name = (ty*)_p; }
    GETP(g_XR, float, XR) GETP(g_Y1, float, Y1)
    GETP(g_QKh, __nv_bfloat16, QKh)
    GETP(g_Vmh, __nv_bfloat16, Vmh)
    GETP(g_XRh, __nv_bfloat16, XRh)
    GETP(g_XPEh, __nv_bfloat16, XPEh)
    GETP(g_ATTh, __nv_bfloat16, ATTh)
    GETP(g_X1h, __nv_bfloat16, X1h)
    GETP(g_Hh, __nv_bfloat16, Hh)
    GETP(g_Wqkh, __nv_bfloat16, Wqkh)
    GETP(g_Wvh, __nv_bfloat16, Wvh)
    GETP(g_Woh, __nv_bfloat16, Woh)
    GETP(g_W1h, __nv_bfloat16, W1h)
    GETP(g_W2h, __nv_bfloat16, W2h)
    GETP(g_bqk, float, bqk)
    GETP(g_part, float2, part) GETP(g_stats, float2, stats)
#undef GETP

    cudaFuncSetAttribute(gemm_mma<true, false, false, false, 2, false>,
                         cudaFuncAttributeMaxDynamicSharedMemorySize, GEMM_DSMEM);
    cudaFuncSetAttribute(gemm_mma<true, true, false, false, 2, false>,
                         cudaFuncAttributeMaxDynamicSharedMemorySize, GEMM_DSMEM);
    cudaFuncSetAttribute(gemm_mma<true, false, true, false, 0, true>,
                         cudaFuncAttributeMaxDynamicSharedMemorySize, GEMM_DSMEM);
    cudaFuncSetAttribute(gemm_mma<true, false, false, true, 3, false>,
                         cudaFuncAttributeMaxDynamicSharedMemorySize, GEMM_DSMEM);

    // 0. weight conversion
    conv_all<<<3073, 256>>>(Wq, Wk, Wv, Wo, W1, W2, bq, bk);

    // 1. transpose + fp16 conversion
    dim3 trGrid(16, 2, Bn * Tn);
    dim3 trBlk(32, 8);
    prep_xr<<<trGrid, trBlk>>>(x, pe, XR, XRh, XPEh);

    // 2. fused Q+K projection, V projection (fp16 out)
    dim3 gQK(1024 / 128, MTOT / 256);
    gemm_mma<true, false, false, false, 2, false><<<gQK, 256, GEMM_DSMEM>>>(
        XPEh, Wqkh, bqk, nullptr, nullptr, nullptr, QKh, 1024, Dn);
    dim3 gD(Dn / 128, MTOT / 256);
    gemm_mma<true, false, false, false, 2, false><<<gD, 256, GEMM_DSMEM>>>(
        XRh, Wvh, bv, nullptr, nullptr, nullptr, Vmh, Dn, Dn);

    // 3. attention (tensor core)
    attn_tc<<<Bn * Hn, 256>>>(QKh, Vmh, adj, hw, ATTh);

    // 4. output projection + residual + fused LN partial sums
    gemm_mma<true, false, true, false, 0, true><<<gD, 256, GEMM_DSMEM>>>(
        ATTh, Woh, bo, XR, nullptr, Y1, nullptr, Dn, Dn);

    // 5. layernorm
    ln_final<<<1, 32>>>(part, stats);
    ln_apply<<<(MTOT * (size_t)Dn / 4) / 256, 256>>>(Y1, stats, g1, be1, X1h);

    // 6. FFN; FFN2 adds fp16 X1 residual and writes transposed output directly
    dim3 gF1(FFn / 128, MTOT / 256);
    gemm_mma<true, true, false, false, 2, false><<<gF1, 256, GEMM_DSMEM>>>(
        X1h, W1h, b1, nullptr, nullptr, nullptr, Hh, FFn, Dn);
    gemm_mma<true, false, false, true, 3, false><<<gD, 256, GEMM_DSMEM>>>(
        Hh, W2h, b2, nullptr, X1h, out, nullptr, Dn, FFn);
}

// round 17
// speedup vs baseline: 1.0977x; 1.0188x over previous
#include <cuda_runtime.h>
#include <cuda_bf16.h>
#include <cuda_fp16.h>
#include <cstdint>
#include <math.h>

#define Bn 32
#define Dn 512
#define Tn 32
#define Nn 64
#define Hn 8
#define DKn 64
#define FFn 2048
#define MTOT (Bn * Nn * Tn)
#define SCALE_F 0.022097086912079608f
#define LN_EPS 1e-5f

// ------------------------------------------------------------------
// Scratch. bf16-typed half buffers hold FP16 bits.
// ------------------------------------------------------------------
__device__ float g_XR[(size_t)MTOT * Dn];
__device__ float g_Y1[(size_t)MTOT * Dn];
__device__ __nv_bfloat16 g_QKh[(size_t)MTOT * 1024];    // fp16
__device__ __nv_bfloat16 g_Vmh[(size_t)MTOT * Dn];      // fp16
__device__ __nv_bfloat16 g_XRh[(size_t)MTOT * Dn];      // fp16
__device__ __nv_bfloat16 g_XPEh[(size_t)MTOT * Dn];     // fp16
__device__ __nv_bfloat16 g_ATTh[(size_t)MTOT * Dn];     // fp16
__device__ __nv_bfloat16 g_X1h[(size_t)MTOT * Dn];      // fp16
__device__ __nv_bfloat16 g_Hh[(size_t)MTOT * FFn];      // fp16
__device__ __nv_bfloat16 g_Wqkh[1024 * Dn];             // fp16
__device__ __nv_bfloat16 g_Wvh[Dn * Dn];                // fp16
__device__ __nv_bfloat16 g_Woh[Dn * Dn];                // fp16
__device__ __nv_bfloat16 g_W1h[FFn * Dn];               // fp16
__device__ __nv_bfloat16 g_W2h[Dn * FFn];               // fp16
__device__ float g_bqk[1024];
__device__ float2 g_part[Bn * 32];
__device__ float2 g_stats[Bn];

// ------------------------------------------------------------------
__device__ __forceinline__ uint32_t smem_u32(const void* p) {
    uint32_t a;
    asm("{ .reg .u64 t; cvta.to.shared.u64 t, %1; cvt.u32.u64 %0, t; }" : "=r"(a) : "l"(p));
    return a;
}
__device__ __forceinline__ void cpasync16(uint32_t dst, const void* src) {
    asm volatile("cp.async.cg.shared.global [%0], [%1], 16;" :: "r"(dst), "l"(src));
}
#define CP_COMMIT() asm volatile("cp.async.commit_group;" ::: "memory")
#define CP_WAIT0() asm volatile("cp.async.wait_group 0;" ::: "memory")
#define CP_WAIT1() asm volatile("cp.async.wait_group 1;" ::: "memory")

#define LDSM4(r0, r1, r2, r3, addr) \
    asm volatile("ldmatrix.sync.aligned.m8n8.x4.shared.b16 {%0,%1,%2,%3}, [%4];" \
                 : "=r"(r0), "=r"(r1), "=r"(r2), "=r"(r3) : "r"(addr))

#define LDSM4T(r0, r1, r2, r3, addr) \
    asm volatile("ldmatrix.sync.aligned.m8n8.x4.trans.shared.b16 {%0,%1,%2,%3}, [%4];" \
                 : "=r"(r0), "=r"(r1), "=r"(r2), "=r"(r3) : "r"(addr))

#define MMA_F16(d, a, b) \
    asm volatile("mma.sync.aligned.m16n8k16.row.col.f32.f16.f16.f32 " \
                 "{%0,%1,%2,%3}, {%4,%5,%6,%7}, {%8,%9}, {%0,%1,%2,%3};" \
                 : "+f"((d)[0]), "+f"((d)[1]), "+f"((d)[2]), "+f"((d)[3]) \
                 : "r"((a)[0]), "r"((a)[1]), "r"((a)[2]), "r"((a)[3]), \
                   "r"((b)[0]), "r"((b)[1]))

__device__ __forceinline__ uint32_t h2bits(float a, float b) {
    __half2 h = __floats2half2_rn(a, b);
    return *(uint32_t*)&h;
}

// ------------------------------------------------------------------
// weight conversion -> fp16; bias concat
// ------------------------------------------------------------------
__global__ void conv_all(const float* __restrict__ Wq, const float* __restrict__ Wk,
                         const float* __restrict__ Wv, const float* __restrict__ Wo,
                         const float* __restrict__ W1, const float* __restrict__ W2,
                         const float* __restrict__ bq, const float* __restrict__ bk) {
    long i4 = (long)blockIdx.x * 256 + threadIdx.x;
    if (i4 >= 786432) {
        int t = threadIdx.x;
        if (blockIdx.x == 3072) {
            g_bqk[t] = bq[t];
            g_bqk[t + 256] = bq[t + 256];
            g_bqk[t + 512] = bk[t];
            g_bqk[t + 768] = bk[t + 256];
        }
        return;
    }
    const float* src;
    __nv_bfloat16* dh;
    long o;
    if (i4 < 65536)       { src = Wq; dh = g_Wqkh;          o = i4; }
    else if (i4 < 131072) { src = Wk; dh = g_Wqkh + 262144; o = i4 - 65536; }
    else if (i4 < 196608) { src = Wv; dh = g_Wvh;           o = i4 - 131072; }
    else if (i4 < 262144) { src = Wo; dh = g_Woh;           o = i4 - 196608; }
    else if (i4 < 524288) { src = W1; dh = g_W1h;           o = i4 - 262144; }
    else                  { src = W2; dh = g_W2h;           o = i4 - 524288; }
    long e = o * 4;
    float4 v = *(const float4*)&src[e];
    *(uint2*)&dh[e] = make_uint2(h2bits(v.x, v.y), h2bits(v.z, v.w));
}

// ------------------------------------------------------------------
__global__ void prep_xr(const float* __restrict__ x, const float* __restrict__ pe,
                        float* __restrict__ XR,
                        __nv_bfloat16* __restrict__ XRh, __nv_bfloat16* __restrict__ XPEh) {
    __shared__ float tile[32][33];
    int bt = blockIdx.z;
    int b = bt >> 5, t = bt & 31;
    int d0 = blockIdx.x * 32, n0 = blockIdx.y * 32;
    size_t bbase = (size_t)b * (Dn * Tn * Nn);
#pragma unroll
    for (int i = 0; i < 4; i++) {
        int d = d0 + threadIdx.y + i * 8;
        tile[threadIdx.y + i * 8][threadIdx.x] =
            x[bbase + (size_t)d * (Tn * Nn) + t * Nn + n0 + threadIdx.x];
    }
    __syncthreads();
    int d = d0 + threadIdx.x;
#pragma unroll
    for (int i = 0; i < 4; i++) {
        int n = n0 + threadIdx.y + i * 8;
        float v = tile[threadIdx.x][threadIdx.y + i * 8];
        size_t idx = bbase + (size_t)n * (Tn * Dn) + t * Dn + d;
        XR[idx] = v;
        __half hv = __float2half_rn(v);
        *(uint16_t*)&XRh[idx] = *(uint16_t*)&hv;
        __half hp = __float2half_rn(v + pe[n * Dn + d]);
        *(uint16_t*)&XPEh[idx] = *(uint16_t*)&hp;
    }
}

// ------------------------------------------------------------------
// fp16 GEMM: 256x128 tile, 256 threads, warp 64x64 (4x2), BK=128,
// 2-stage, 1 barrier/iter, pitch-272 smem, prefetch spread over 6 kc.
// OUTM_: 0=float, 2=fp16, 3=direct-transposed output (B,D,T,N).
// ------------------------------------------------------------------
#define PITCHB 272
#define STG_B (384 * PITCHB)            // 104448
#define GEMM_DSMEM (2 * STG_B)          // 208896
#define TPITCH 260

template <bool BIAS_, bool RELU_, bool RESID_, bool RESH_, int OUTM_, bool LNP_>
__global__ void __launch_bounds__(256, 1)
gemm_mma(const __nv_bfloat16* __restrict__ Ah, const __nv_bfloat16* __restrict__ Wh,
         const float* __restrict__ bias, const float* __restrict__ Rsd,
         const __nv_bfloat16* __restrict__ RsdH,
         float* __restrict__ Cf, __nv_bfloat16* __restrict__ Ch,
         int Ncols, int K) {
    constexpr uint32_t oAH = 0;
    constexpr uint32_t oBH = 256 * PITCHB;

    extern __shared__ char smraw[];
    const uint32_t sb = smem_u32(smraw);
    const int tid = threadIdx.x;
    const int wid = tid >> 5;
    const int lane = tid & 31;
    const size_t rowBase = (size_t)blockIdx.y * 256;
    const int colBase = blockIdx.x * 128;
    const int wm = (wid >> 1) * 64;
    const int wn = (wid & 1) * 64;

    float acc[4][8][4];
#pragma unroll
    for (int mt = 0; mt < 4; mt++)
#pragma unroll
        for (int nt = 0; nt < 8; nt++)
#pragma unroll
            for (int q = 0; q < 4; q++) acc[mt][nt][q] = 0.f;

    const int KIT = K >> 7;

    auto load64 = [&](uint32_t sdst, const __nv_bfloat16* g, size_t row0, int k0, int r0) {
        const char* gbase = (const char*)(g + (row0 + r0) * (size_t)K + k0);
        size_t rs = (size_t)K * 2;
#pragma unroll
        for (int q = 0; q < 4; q++) {
            int ch = tid + q * 256;
            int r = ch >> 4, c = ch & 15;
            cpasync16(sdst + (r0 + r) * PITCHB + c * 16, gbase + (size_t)r * rs + c * 16);
        }
    };

#pragma unroll
    for (int r0 = 0; r0 < 256; r0 += 64) load64(sb + oAH, Ah, rowBase, 0, r0);
    load64(sb + oBH, Wh, (size_t)colBase, 0, 0);
    load64(sb + oBH, Wh, (size_t)colBase, 0, 64);
    CP_COMMIT();

    const int arow = lane & 15;
    const int ainc = lane >> 4;
    const int brow = (lane & 7) + ((lane >> 4) << 3);
    const int binc = (lane >> 3) & 1;

    for (int it = 0; it < KIT; ++it) {
        CP_WAIT0();
        __syncthreads();
        const bool pf = (it + 1 < KIT);
        const uint32_t stn = sb + ((it + 1) & 1) * STG_B;
        const int k0n = (it + 1) * 128;
        const uint32_t stb = sb + (it & 1) * STG_B;
#pragma unroll
        for (int kc = 0; kc < 8; kc++) {
            uint32_t ah[4][4], bh[8][2];
#pragma unroll
            for (int mt = 0; mt < 4; mt++) {
                uint32_t ad = stb + oAH + (wm + mt * 16 + arow) * PITCHB + kc * 32 + ainc * 16;
                LDSM4(ah[mt][0], ah[mt][1], ah[mt][2], ah[mt][3], ad);
            }
#pragma unroll
            for (int bt = 0; bt < 4; bt++) {
                uint32_t bd = stb + oBH + (wn + bt * 16 + brow) * PITCHB + kc * 32 + binc * 16;
                uint32_t r0, r1, r2, r3;
                LDSM4(r0, r1, r2, r3, bd);
                bh[2 * bt][0] = r0; bh[2 * bt][1] = r1;
                bh[2 * bt + 1][0] = r2; bh[2 * bt + 1][1] = r3;
            }
            if (pf) {
                if (kc < 4)       load64(stn + oAH, Ah, rowBase, k0n, kc * 64);
                else if (kc == 4) load64(stn + oBH, Wh, (size_t)colBase, k0n, 0);
                else if (kc == 5) load64(stn + oBH, Wh, (size_t)colBase, k0n, 64);
            }
#pragma unroll
            for (int mt = 0; mt < 4; mt++) {
#pragma unroll
                for (int nt = 0; nt < 8; nt++) {
                    MMA_F16(acc[mt][nt], ah[mt], bh[nt]);
                }
            }
        }
        CP_COMMIT();
    }

    float* sT = (float*)smraw;
    if (OUTM_ == 3) __syncthreads();

    float lns = 0.f, lns2 = 0.f;
#pragma unroll
    for (int mt = 0; mt < 4; mt++) {
#pragma unroll
        for (int nt = 0; nt < 8; nt++) {
            const int colL = wn + nt * 8 + (lane & 3) * 2;
            const int col = colBase + colL;
#pragma unroll
            for (int half = 0; half < 2; half++) {
                const int rowL = wm + mt * 16 + (lane >> 2) + half * 8;
                const size_t row = rowBase + rowL;
                float vx = acc[mt][nt][half * 2 + 0];
                float vy = acc[mt][nt][half * 2 + 1];
                if (BIAS_) {
                    float2 bv = *(const float2*)&bias[col];
                    vx += bv.x; vy += bv.y;
                }
                if (RELU_) { vx = fmaxf(vx, 0.f); vy = fmaxf(vy, 0.f); }
                if (RESID_) {
                    float2 rv = *(const float2*)&Rsd[row * Ncols + col];
                    vx += rv.x; vy += rv.y;
                }
                if (RESH_) {
                    __half2 rh = *(const __half2*)&RsdH[row * Ncols + col];
                    vx += __low2float(rh); vy += __high2float(rh);
                }
                if (LNP_) {
                    lns += vx + vy;
                    lns2 += vx * vx + vy * vy;
                }
                if (OUTM_ == 0) {
                    *(float2*)&Cf[row * Ncols + col] = make_float2(vx, vy);
                } else if (OUTM_ == 2) {
                    *(uint32_t*)&Ch[row * Ncols + col] = h2bits(vx, vy);
                } else {
                    sT[colL * TPITCH + rowL] = vx;
                    sT[(colL + 1) * TPITCH + rowL] = vy;
                }
            }
        }
    }

    if (OUTM_ == 3) {
        __syncthreads();
        const int b = (int)blockIdx.y >> 3;
        const int nb = ((int)blockIdx.y & 7) * 8;
#pragma unroll
        for (int p = 0; p < 16; p++) {
            int idx = p * 256 + tid;
            int d = idx >> 5, t = idx & 31;
            float v[8];
#pragma unroll
            for (int nl = 0; nl < 8; nl++) v[nl] = sT[d * TPITCH + nl * 32 + t];
            size_t o = (((size_t)(b * Dn + colBase + d) * Tn) + t) * Nn + nb;
            *(float4*)&Cf[o] = make_float4(v[0], v[1], v[2], v[3]);
            *(float4*)&Cf[o + 4] = make_float4(v[4], v[5], v[6], v[7]);
        }
    }

    if (LNP_) {
        __syncthreads();
        float* rs = (float*)smraw;
        float* rs2 = rs + 256;
        rs[tid] = lns; rs2[tid] = lns2;
        __syncthreads();
        for (int o = 128; o; o >>= 1) {
            if (tid < o) {
                rs[tid] += rs[tid + o];
                rs2[tid] += rs2[tid + o];
            }
            __syncthreads();
        }
        if (tid == 0) {
            int pidx = ((int)blockIdx.y >> 3) * 32 + ((int)blockIdx.y & 7) * 4 + blockIdx.x;
            g_part[pidx] = make_float2(rs[0], rs2[0]);
        }
    }
}

// ------------------------------------------------------------------
// Tensor-core attention, depth-3 pipelined chunk loads (dynamic smem).
// Layout: sQb[3] @0, sKb[3] @27648, sA @55296, sS @64512 (81920 total)
// ------------------------------------------------------------------
#define AP 144
#define ATT_DSMEM 81920
__global__ void __launch_bounds__(256)
attn_tc(const __nv_bfloat16* __restrict__ QKh, const __nv_bfloat16* __restrict__ Vmh,
        const float* __restrict__ adj, const float* __restrict__ hw,
        __nv_bfloat16* __restrict__ ATTh) {
    extern __shared__ char asm_[];
    const uint32_t sbase = smem_u32(asm_);
    char* sA = asm_ + 55296;
    float* sS = (float*)(asm_ + 64512);   // [64][68]

    const int b = blockIdx.x >> 3;
    const int h = blockIdx.x & 7;
    const int tid = threadIdx.x;
    const int wid = tid >> 5;
    const int lane = tid & 31;
    const int wm = (wid >> 1) * 16;
    const int wn = (wid & 1) * 32;
    const uint32_t uA = sbase + 55296;

    const int arow = lane & 15;
    const int ainc = lane >> 4;
    const int brow = (lane & 7) + ((lane >> 4) << 3);
    const int binc = (lane >> 3) & 1;
    const int tkrow = (lane & 7) + (((lane >> 3) & 1) << 3);
    const int tncol = (lane >> 4) * 8;

    const size_t tokBase = (size_t)b * 2048;
    const int lr = tid >> 3;
    const int lc = tid & 7;

    auto issue_qk = [&](int buf, int t0) {
        uint32_t uQ = sbase + buf * 9216;
        uint32_t uK = sbase + 27648 + buf * 9216;
#pragma unroll
        for (int j = 0; j < 2; j++) {
            int r = lr + j * 32;
            const __nv_bfloat16* qsrc = QKh + (tokBase + r * 32 + t0) * 1024 + h * DKn;
            cpasync16(uQ + r * AP + lc * 16, (const char*)qsrc + lc * 16);
            cpasync16(uK + r * AP + lc * 16, (const char*)(qsrc + 512) + lc * 16);
        }
        CP_COMMIT();
    };
    auto issue_v = [&](int buf, int t0) {
        uint32_t uV = sbase + buf * 9216;
#pragma unroll
        for (int j = 0; j < 2; j++) {
            int r = lr + j * 32;
            const __nv_bfloat16* vsrc = Vmh + (tokBase + r * 32 + t0) * 512 + h * DKn;
            cpasync16(uV + r * AP + lc * 16, (const char*)vsrc + lc * 16);
        }
        CP_COMMIT();
    };

    float acc[4][4];
#pragma unroll
    for (int nt = 0; nt < 4; nt++)
#pragma unroll
        for (int q = 0; q < 4; q++) acc[nt][q] = 0.f;

    // ---- phase 1: S = Q K^T, depth-3 pipelined ----
    issue_qk(0, 0);
    issue_qk(1, 1);
    for (int t0 = 0; t0 < 32; t0++) {
        if (t0 < 30) CP_WAIT1(); else CP_WAIT0();
        __syncthreads();
        if (t0 + 2 < 32) issue_qk((t0 + 2) % 3, t0 + 2);
        const uint32_t uQ = sbase + (t0 % 3) * 9216;
        const uint32_t uK = sbase + 27648 + (t0 % 3) * 9216;
#pragma unroll
        for (int kc = 0; kc < 4; kc++) {
            uint32_t a[4], bf[4][2];
            LDSM4(a[0], a[1], a[2], a[3], uQ + (wm + arow) * AP + kc * 32 + ainc * 16);
#pragma unroll
            for (int bt = 0; bt < 2; bt++) {
                uint32_t r0, r1, r2, r3;
                LDSM4(r0, r1, r2, r3, uK + (wn + bt * 16 + brow) * AP + kc * 32 + binc * 16);
                bf[2 * bt][0] = r0; bf[2 * bt][1] = r1;
                bf[2 * bt + 1][0] = r2; bf[2 * bt + 1][1] = r3;
            }
#pragma unroll
            for (int nt = 0; nt < 4; nt++) MMA_F16(acc[nt], a, bf[nt]);
        }
    }

    // S -> smem (scaled)
    __syncthreads();
#pragma unroll
    for (int nt = 0; nt < 4; nt++) {
        int col = wn + nt * 8 + (lane & 3) * 2;
#pragma unroll
        for (int half = 0; half < 2; half++) {
            int row = wm + (lane >> 2) + half * 8;
            sS[row * 68 + col] = acc[nt][half * 2] * SCALE_F;
            sS[row * 68 + col + 1] = acc[nt][half * 2 + 1] * SCALE_F;
        }
    }
    __syncthreads();

    // phase-2 prologue: V chunks 0,1 load under softmax
    issue_v(0, 0);
    issue_v(1, 1);

    // softmax * hw + adj
    {
        const int w = wid, ln2 = lane;
        const float hwv = hw[h];
        for (int rr = 0; rr < 8; rr++) {
            int row = w * 8 + rr;
            float v0 = sS[row * 68 + ln2];
            float v1 = sS[row * 68 + ln2 + 32];
            float mx = fmaxf(v0, v1);
#pragma unroll
            for (int o = 16; o; o >>= 1) mx = fmaxf(mx, __shfl_xor_sync(0xffffffffu, mx, o));
            float e0 = __expf(v0 - mx), e1 = __expf(v1 - mx);
            float s = e0 + e1;
#pragma unroll
            for (int o = 16; o; o >>= 1) s += __shfl_xor_sync(0xffffffffu, s, o);
            float inv = 1.f / s;
            size_t ab = (size_t)h * 4096 + row * 64;
            sS[row * 68 + ln2]      = e0 * inv * hwv + adj[ab + ln2];
            sS[row * 68 + ln2 + 32] = e1 * inv * hwv + adj[ab + 32 + ln2];
        }
    }
    __syncthreads();

    // convert weights to fp16 tile sA[q][m]
    {
        int q = tid >> 2, mb = (tid & 3) * 16;
#pragma unroll
        for (int m = 0; m < 16; m += 2) {
            *(uint32_t*)(sA + q * AP + (mb + m) * 2) = h2bits(sS[q * 68 + mb + m], sS[q * 68 + mb + m + 1]);
        }
    }

    // ---- phase 2: O = A V, depth-3 pipelined ----
    for (int t0 = 0; t0 < 32; t0++) {
        if (t0 < 30) CP_WAIT1(); else CP_WAIT0();
        __syncthreads();
        if (t0 + 2 < 32) issue_v((t0 + 2) % 3, t0 + 2);
        const uint32_t uV = sbase + (t0 % 3) * 9216;
        float o2[4][4];
#pragma unroll
        for (int nt = 0; nt < 4; nt++)
#pragma unroll
            for (int q = 0; q < 4; q++) o2[nt][q] = 0.f;
#pragma unroll
        for (int kc = 0; kc < 4; kc++) {
            uint32_t a[4], bf[4][2];
            LDSM4(a[0], a[1], a[2], a[3], uA + (wm + arow) * AP + kc * 32 + ainc * 16);
#pragma unroll
            for (int bt = 0; bt < 2; bt++) {
                uint32_t r0, r1, r2, r3;
                LDSM4T(r0, r1, r2, r3,
                       uV + (kc * 16 + tkrow) * AP + (wn + bt * 16 + tncol) * 2);
                bf[2 * bt][0] = r0; bf[2 * bt][1] = r1;
                bf[2 * bt + 1][0] = r2; bf[2 * bt + 1][1] = r3;
            }
#pragma unroll
            for (int nt = 0; nt < 4; nt++) MMA_F16(o2[nt], a, bf[nt]);
        }
#pragma unroll
        for (int nt = 0; nt < 4; nt++) {
            int dk = wn + nt * 8 + (lane & 3) * 2;
#pragma unroll
            for (int half = 0; half < 2; half++) {
                int qrow = wm + (lane >> 2) + half * 8;
                size_t off = (tokBase + qrow * 32 + t0) * 512 + h * DKn + dk;
                *(uint32_t*)&ATTh[off] = h2bits(o2[nt][half * 2], o2[nt][half * 2 + 1]);
            }
        }
    }
}

// ------------------------------------------------------------------
// LayerNorm (partials fused into Wo epilogue)
// ------------------------------------------------------------------
__global__ void ln_final(const float2* __restrict__ part, float2* __restrict__ stats) {
    int b = threadIdx.x;
    if (b < Bn) {
        float s = 0.f, s2 = 0.f;
        for (int c = 0; c < 32; c++) {
            float2 p = part[b * 32 + c];
            s += p.x; s2 += p.y;
        }
        const float invN = 1.0f / 1048576.0f;
        float mean = s * invN;
        float var = s2 * invN - mean * mean;
        stats[b] = make_float2(mean, rsqrtf(var + LN_EPS));
    }
}

__global__ void ln_apply(const float* __restrict__ Y1, const float2* __restrict__ stats,
                         const float* __restrict__ g1, const float* __restrict__ be1,
                         __nv_bfloat16* __restrict__ X1h) {
    size_t e = ((size_t)blockIdx.x * blockDim.x + threadIdx.x) * 4;
    float2 st = stats[e >> 20];
    size_t gi = e & 1048575;
    float4 y = *(const float4*)&Y1[e];
    float4 g = *(const float4*)&g1[gi];
    float4 be = *(const float4*)&be1[gi];
    float4 o;
    o.x = (y.x - st.x) * st.y * g.x + be.x;
    o.y = (y.y - st.x) * st.y * g.y + be.y;
    o.z = (y.z - st.x) * st.y * g.z + be.z;
    o.w = (y.w - st.x) * st.y * g.w + be.w;
    *(uint2*)&X1h[e] = make_uint2(h2bits(o.x, o.y), h2bits(o.z, o.w));
}

// ------------------------------------------------------------------
extern "C" void kernel_launch(void* const* d_in, const int* in_sizes, int n_in,
                              void* d_out, int out_size) {
    const float* x   = (const float*)d_in[0];
    const float* Wq  = (const float*)d_in[1];
    const float* bq  = (const float*)d_in[2];
    const float* Wk  = (const float*)d_in[3];
    const float* bk  = (const float*)d_in[4];
    const float* Wv  = (const float*)d_in[5];
    const float* bv  = (const float*)d_in[6];
    const float* Wo  = (const float*)d_in[7];
    const float* bo  = (const float*)d_in[8];
    const float* W1  = (const float*)d_in[9];
    const float* b1  = (const float*)d_in[10];
    const float* W2  = (const float*)d_in[11];
    const float* b2  = (const float*)d_in[12];
    const float* g1  = (const float*)d_in[13];
    const float* be1 = (const float*)d_in[14];
    const float* adj = (const float*)d_in[15];
    const float* hw  = (const float*)d_in[16];
    const float* pe  = (const float*)d_in[17];
    float* out = (float*)d_out;

#define GETP(sym, ty, name) ty* name; { void* _p; cudaGetSymbolAddress(&_p, sym); name = (ty*)_p; }
    GETP(g_XR, float, XR) GETP(g_Y1, float, Y1)
    GETP(g_QKh, __nv_bfloat16, QKh)
    GETP(g_Vmh, __nv_bfloat16, Vmh)
    GETP(g_XRh, __nv_bfloat16, XRh)
    GETP(g_XPEh, __nv_bfloat16, XPEh)
    GETP(g_ATTh, __nv_bfloat16, ATTh)
    GETP(g_X1h, __nv_bfloat16, X1h)
    GETP(g_Hh, __nv_bfloat16, Hh)
    GETP(g_Wqkh, __nv_bfloat16, Wqkh)
    GETP(g_Wvh, __nv_bfloat16, Wvh)
    GETP(g_Woh, __nv_bfloat16, Woh)
    GETP(g_W1h, __nv_bfloat16, W1h)
    GETP(g_W2h, __nv_bfloat16, W2h)
    GETP(g_bqk, float, bqk)
    GETP(g_part, float2, part) GETP(g_stats, float2, stats)
#undef GETP

    cudaFuncSetAttribute(gemm_mma<true, false, false, false, 2, false>,
                         cudaFuncAttributeMaxDynamicSharedMemorySize, GEMM_DSMEM);
    cudaFuncSetAttribute(gemm_mma<true, true, false, false, 2, false>,
                         cudaFuncAttributeMaxDynamicSharedMemorySize, GEMM_DSMEM);
    cudaFuncSetAttribute(gemm_mma<true, false, true, false, 0, true>,
                         cudaFuncAttributeMaxDynamicSharedMemorySize, GEMM_DSMEM);
    cudaFuncSetAttribute(gemm_mma<true, false, false, true, 3, false>,
                         cudaFuncAttributeMaxDynamicSharedMemorySize, GEMM_DSMEM);
    cudaFuncSetAttribute(attn_tc,
                         cudaFuncAttributeMaxDynamicSharedMemorySize, ATT_DSMEM);

    // 0. weight conversion
    conv_all<<<3073, 256>>>(Wq, Wk, Wv, Wo, W1, W2, bq, bk);

    // 1. transpose + fp16 conversion
    dim3 trGrid(16, 2, Bn * Tn);
    dim3 trBlk(32, 8);
    prep_xr<<<trGrid, trBlk>>>(x, pe, XR, XRh, XPEh);

    // 2. fused Q+K projection, V projection (fp16 out)
    dim3 gQK(1024 / 128, MTOT / 256);
    gemm_mma<true, false, false, false, 2, false><<<gQK, 256, GEMM_DSMEM>>>(
        XPEh, Wqkh, bqk, nullptr, nullptr, nullptr, QKh, 1024, Dn);
    dim3 gD(Dn / 128, MTOT / 256);
    gemm_mma<true, false, false, false, 2, false><<<gD, 256, GEMM_DSMEM>>>(
        XRh, Wvh, bv, nullptr, nullptr, nullptr, Vmh, Dn, Dn);

    // 3. attention (tensor core, pipelined)
    attn_tc<<<Bn * Hn, 256, ATT_DSMEM>>>(QKh, Vmh, adj, hw, ATTh);

    // 4. output projection + residual + fused LN partial sums
    gemm_mma<true, false, true, false, 0, true><<<gD, 256, GEMM_DSMEM>>>(
        ATTh, Woh, bo, XR, nullptr, Y1, nullptr, Dn, Dn);

    // 5. layernorm
    ln_final<<<1, 32>>>(part, stats);
    ln_apply<<<(MTOT * (size_t)Dn / 4) / 256, 256>>>(Y1, stats, g1, be1, X1h);

    // 6. FFN; FFN2 adds fp16 X1 residual and writes transposed output directly
    dim3 gF1(FFn / 128, MTOT / 256);
    gemm_mma<true, true, false, false, 2, false><<<gF1, 256, GEMM_DSMEM>>>(
        X1h, W1h, b1, nullptr, nullptr, nullptr, Hh, FFn, Dn);
    gemm_mma<true, false, false, true, 3, false><<<gD, 256, GEMM_DSMEM>>>(
        Hh, W2h, b2, nullptr, X1h, out, nullptr, Dn, FFn);
}